// round 10
// baseline (speedup 1.0000x reference)
#include <cuda_runtime.h>
#include <cuda_bf16.h>
#include <math.h>
#include <float.h>
#include <stdint.h>

typedef __nv_bfloat16 bf;

// ---------------- problem constants ----------------
#define B_    32
#define LE_   512
#define LD_   592
#define LP_   640
#define DM_   512
#define DFF_  2048
#define NC_   7
#define NM_   4
#define LBL_  256
#define PRED_ 336
#define KT_E  18
#define KT_D  19

// ---------------- fp32 workspace ----------------
#define SZ_XE  ((size_t)B_*LE_*DM_)
#define SZ_XD  ((size_t)B_*LD_*DM_)

#define O_XE   ((size_t)0)
#define O_XA   (O_XE + SZ_XE)
#define O_XD   (O_XA + SZ_XD)
#define O_Q    (O_XD + SZ_XD)
#define O_V    (O_Q  + SZ_XD)
#define O_T    (O_V  + SZ_XD)
#define O_CORR (O_T  + SZ_XD)
#define O_ENC  (O_CORR + (size_t)B_*LD_)
#define O_TS   (O_ENC + SZ_XE)
#define O_SEA  (O_TS + SZ_XD)
#define O_MEAN (O_SEA + (size_t)B_*LE_*NC_)
#define O_WGT  (O_MEAN + (size_t)B_*NC_)
#define WS_TOTAL (O_WGT + (size_t)B_*32)

__device__ __align__(256) float g_ws[WS_TOTAL];
__device__ int g_delay[B_*32];

// ---------------- bf16 split workspace ----------------
#define SZ_AB  ((size_t)B_*LP_*DM_)
#define SZ_QB  ((size_t)B_*LP_*DM_)
#define SZ_KB  ((size_t)B_*LP_*DM_)
#define SZ_HB  ((size_t)B_*LD_*DFF_)
#define OW_EATT ((size_t)0)
#define OW_EW1  ((size_t)2097152)
#define OW_EW2  ((size_t)4194304)
#define OW_SW   ((size_t)6291456)
#define OW_CW   ((size_t)7340032)
#define OW_DW1  ((size_t)8388608)
#define OW_DW2  ((size_t)9437184)
#define SZ_WB   ((size_t)10485760)

__device__ __align__(256) bf g_abh[SZ_AB];
__device__ __align__(256) bf g_abl[SZ_AB];
__device__ __align__(256) bf g_qbh[SZ_QB];
__device__ __align__(256) bf g_qbl[SZ_QB];
__device__ __align__(256) bf g_kbh[SZ_KB];
__device__ __align__(256) bf g_kbl[SZ_KB];
__device__ __align__(256) bf g_hbh[SZ_HB];
__device__ __align__(256) bf g_hbl[SZ_HB];
__device__ __align__(256) bf g_wbh[SZ_WB];
__device__ __align__(256) bf g_wbl[SZ_WB];

// ---------------- helpers ----------------
__device__ __forceinline__ float gelu_exact(float v) {
    return 0.5f * v * (1.0f + erff(v * 0.70710678118654752440f));
}
__device__ __forceinline__ uint32_t s2u(const void* p){
    uint32_t a;
    asm("{ .reg .u64 t; cvta.to.shared.u64 t, %1; cvt.u32.u64 %0, t; }":"=r"(a):"l"(p));
    return a;
}
#define SWZ(o) ((o) ^ (((o)>>3)&0x70))

#define LDSM4(r, ad) \
    asm volatile("ldmatrix.sync.aligned.m8n8.x4.shared.b16 {%0,%1,%2,%3}, [%4];" \
        : "=r"((r)[0]), "=r"((r)[1]), "=r"((r)[2]), "=r"((r)[3]) : "r"(ad))

#define MMA16816(d, a, b0, b1) \
    asm volatile("mma.sync.aligned.m16n8k16.row.col.f32.bf16.bf16.f32 " \
        "{%0,%1,%2,%3}, {%4,%5,%6,%7}, {%8,%9}, {%0,%1,%2,%3};" \
        : "+f"((d)[0]), "+f"((d)[1]), "+f"((d)[2]), "+f"((d)[3]) \
        : "r"((a)[0]), "r"((a)[1]), "r"((a)[2]), "r"((a)[3]), "r"(b0), "r"(b1))

__device__ __forceinline__ void split_store(bf* H, bf* L, size_t o, float v0, float v1){
    bf h0 = __float2bfloat16(v0), h1 = __float2bfloat16(v1);
    bf l0 = __float2bfloat16(v0 - __bfloat162float(h0));
    bf l1 = __float2bfloat16(v1 - __bfloat162float(h1));
    *(__nv_bfloat162*)(H + o) = __nv_bfloat162(h0, h1);
    *(__nv_bfloat162*)(L + o) = __nv_bfloat162(l0, l1);
}

// ---------------- fused weight transpose+split ----------------
__global__ void k_cvtT_all(const float* __restrict__ eatt, const float* __restrict__ e1,
                           const float* __restrict__ e2, const float* __restrict__ sw,
                           const float* __restrict__ cw, const float* __restrict__ d1,
                           const float* __restrict__ d2,
                           bf* __restrict__ WH, bf* __restrict__ WL){
    __shared__ float t[32][33];
    int blk = blockIdx.x;
    const float* src; size_t dstoff; int K, N, mi, tt;
    if (blk < 2048)       { src=eatt; dstoff=OW_EATT; K=512; N=512;  mi=blk/256;        tt=blk%256; }
    else if (blk < 4096)  { src=e1;   dstoff=OW_EW1;  K=512; N=2048; mi=(blk-2048)/1024; tt=(blk-2048)%1024; }
    else if (blk < 6144)  { src=e2;   dstoff=OW_EW2;  K=2048;N=512;  mi=(blk-4096)/1024; tt=(blk-4096)%1024; }
    else if (blk < 7168)  { src=sw;   dstoff=OW_SW;   K=512; N=512;  mi=(blk-6144)/256;  tt=(blk-6144)%256; }
    else if (blk < 8192)  { src=cw;   dstoff=OW_CW;   K=512; N=512;  mi=(blk-7168)/256;  tt=(blk-7168)%256; }
    else if (blk < 9216)  { src=d1;   dstoff=OW_DW1;  K=512; N=2048; mi=0;               tt=blk-8192; }
    else                  { src=d2;   dstoff=OW_DW2;  K=2048;N=512;  mi=0;               tt=blk-9216; }
    int tn = N/32;
    int n0 = (tt % tn)*32, k0 = (tt / tn)*32;
    const float* W = src + (size_t)mi*K*N;
    bf* TH = WH + dstoff + (size_t)mi*K*N;
    bf* TL = WL + dstoff + (size_t)mi*K*N;
    int tx = threadIdx.x, ty = threadIdx.y;
    #pragma unroll
    for (int i = 0; i < 32; i += 8)
        t[ty+i][tx] = W[(size_t)(k0+ty+i)*N + n0 + tx];
    __syncthreads();
    #pragma unroll
    for (int i = 0; i < 32; i += 8) {
        float x = t[tx][ty+i];
        bf h = __float2bfloat16(x);
        size_t o = (size_t)(n0+ty+i)*K + k0 + tx;
        TH[o] = h; TL[o] = __float2bfloat16(x - __bfloat162float(h));
    }
}

// ---------------- bf16x3 mma.sync GEMM, routed epilogue ----------------
// mode 0: C fp32 dense (+ optional RES residual add)
// mode 1: split H0/L0, padded rows (Lv->Lp), ld ldh0
// mode 2/3: col-routed QKV / KV (split padded + fp32 tail)
// mode 4: Gram->corr fused reduction (C = corr, cB = L)
#define SMEM_SZ 131072

__device__ __forceinline__ void ldchunk(uint32_t st,
    const bf* __restrict__ A_h, const bf* __restrict__ A_l, int lda,
    const bf* __restrict__ B_h, const bf* __restrict__ B_l, int ldb,
    int k0, int tid)
{
    const bf* srcs[4] = {A_h, A_l, B_h, B_l};
    const int lds[4] = {lda, lda, ldb, ldb};
    #pragma unroll
    for (int t = 0; t < 4; t++) {
        #pragma unroll
        for (int i = 0; i < 4; i++) {
            int idx = i*256 + tid;
            int row = idx >> 3, c16 = idx & 7;
            uint32_t dst = st + t*16384 + SWZ(row*128 + c16*16);
            const bf* src = srcs[t] + (size_t)row*lds[t] + k0 + c16*8;
            asm volatile("cp.async.cg.shared.global [%0], [%1], 16;\n"::"r"(dst),"l"(src));
        }
    }
    asm volatile("cp.async.commit_group;\n":::"memory");
}

__global__ void __launch_bounds__(256,1) k_mma(
    const bf* __restrict__ Ah, const bf* __restrict__ Al, int lda,
    const bf* __restrict__ Bh, const bf* __restrict__ Bl, int ldb,
    int K, int rowsV, int colsV,
    long long aB, long long bB, long long cB,
    int mode, float* __restrict__ C, int ldc,
    bf* __restrict__ H0, bf* __restrict__ L0, int ldh0,
    bf* __restrict__ H1, bf* __restrict__ L1,
    int Lv, int Lp, int nq, int nk,
    const float* __restrict__ RES, const float* __restrict__ bias, int act)
{
    extern __shared__ char smem[];
    uint32_t sb0 = s2u(smem);
    const int tid = threadIdx.x, lane = tid & 31, wid = tid >> 5;
    const int bn = blockIdx.x, bm = blockIdx.y, bz = blockIdx.z;
    const bf* Ah2 = Ah + (size_t)bz*aB + (size_t)bm*128*lda;
    const bf* Al2 = Al + (size_t)bz*aB + (size_t)bm*128*lda;
    const bf* Bh2 = Bh + (size_t)bz*bB + (size_t)bn*128*ldb;
    const bf* Bl2 = Bl + (size_t)bz*bB + (size_t)bn*128*ldb;
    if (C) C += (size_t)bz*cB;

    float acc[4][4][4];
    #pragma unroll
    for (int i = 0; i < 4; i++)
        #pragma unroll
        for (int j = 0; j < 4; j++)
            #pragma unroll
            for (int q = 0; q < 4; q++) acc[i][j][q] = 0.f;

    const int KC = K >> 6;
    const int m0 = (wid & 1) << 6, n0 = (wid >> 1) << 5;

    ldchunk(sb0, Ah2, Al2, lda, Bh2, Bl2, ldb, 0, tid);

    for (int c = 0; c < KC; c++) {
        uint32_t st = sb0 + (uint32_t)(c & 1) * 65536u;
        if (c+1 < KC) {
            ldchunk(sb0 + (uint32_t)((c+1) & 1) * 65536u,
                    Ah2, Al2, lda, Bh2, Bl2, ldb, (c+1)*64, tid);
            asm volatile("cp.async.wait_group 1;\n":::"memory");
        } else {
            asm volatile("cp.async.wait_group 0;\n":::"memory");
        }
        __syncthreads();

        #pragma unroll
        for (int kk = 0; kk < 4; kk++) {
            uint32_t afh[4][4], afl[4][4], bfh[2][4], bfl[2][4];
            #pragma unroll
            for (int mt = 0; mt < 4; mt++) {
                int m = m0 + mt*16 + (lane & 15);
                int kb = kk*32 + ((lane >> 4) << 4);
                uint32_t off = SWZ(m*128 + kb);
                LDSM4(afh[mt], st + off);
                LDSM4(afl[mt], st + 16384u + off);
            }
            #pragma unroll
            for (int nt2 = 0; nt2 < 2; nt2++) {
                int g = lane >> 3;
                int n = n0 + nt2*16 + ((g >> 1) << 3) + (lane & 7);
                int kb = kk*32 + ((g & 1) << 4);
                uint32_t off = SWZ(n*128 + kb);
                LDSM4(bfh[nt2], st + 32768u + off);
                LDSM4(bfl[nt2], st + 49152u + off);
            }
            #pragma unroll
            for (int mt = 0; mt < 4; mt++)
                #pragma unroll
                for (int nt = 0; nt < 4; nt++)
                    MMA16816(acc[mt][nt], afh[mt],
                             bfh[nt>>1][(nt&1)*2], bfh[nt>>1][(nt&1)*2+1]);
            #pragma unroll
            for (int mt = 0; mt < 4; mt++)
                #pragma unroll
                for (int nt = 0; nt < 4; nt++)
                    MMA16816(acc[mt][nt], afh[mt],
                             bfl[nt>>1][(nt&1)*2], bfl[nt>>1][(nt&1)*2+1]);
            #pragma unroll
            for (int mt = 0; mt < 4; mt++)
                #pragma unroll
                for (int nt = 0; nt < 4; nt++)
                    MMA16816(acc[mt][nt], afl[mt],
                             bfh[nt>>1][(nt&1)*2], bfh[nt>>1][(nt&1)*2+1]);
        }
        __syncthreads();
    }

    const int gid = lane >> 2, tig = lane & 3;

    if (mode == 4) {
        // Gram -> mean_corr fused: diagonal reduction of this 128x128 tile
        float* cs = (float*)smem;
        int L = Lv;
        for (int i = tid; i < L; i += 256) cs[i] = 0.f;
        __syncthreads();
        #pragma unroll
        for (int mt = 0; mt < 4; mt++) {
            #pragma unroll
            for (int h = 0; h < 2; h++) {
                int row = bm*128 + m0 + mt*16 + gid + h*8;
                if (row >= rowsV) continue;
                #pragma unroll
                for (int nt = 0; nt < 4; nt++) {
                    int col = bn*128 + n0 + nt*8 + tig*2;
                    if (col >= colsV) continue;
                    int tau0 = row - col; if (tau0 < 0) tau0 += L;
                    atomicAdd(&cs[tau0], acc[mt][nt][h*2+0]);
                    int tau1 = tau0 - 1; if (tau1 < 0) tau1 += L;
                    atomicAdd(&cs[tau1], acc[mt][nt][h*2+1]);
                }
            }
        }
        __syncthreads();
        for (int i = tid; i < L; i += 256)
            atomicAdd(&C[i], cs[i] * (1.0f/DM_));
        return;
    }

    const int nq128 = nq*128, nqk128 = (nq+nk)*128;
    #pragma unroll
    for (int mt = 0; mt < 4; mt++) {
        #pragma unroll
        for (int h = 0; h < 2; h++) {
            int row = bm*128 + m0 + mt*16 + gid + h*8;
            if (row >= rowsV) continue;
            int bq = row / Lv, rr = row - bq*Lv;
            size_t prow = (size_t)bq*Lp + rr;
            #pragma unroll
            for (int nt = 0; nt < 4; nt++) {
                int col = bn*128 + n0 + nt*8 + tig*2;
                if (col >= colsV) continue;
                float v0 = acc[mt][nt][h*2+0];
                float v1 = acc[mt][nt][h*2+1];
                if (bias) { v0 += bias[col]; v1 += bias[col+1]; }
                if (act)  { v0 = gelu_exact(v0); v1 = gelu_exact(v1); }
                if (mode == 0) {
                    size_t o = (size_t)row*ldc + col;
                    if (RES) { float2 r2 = *(const float2*)(RES + o); v0 += r2.x; v1 += r2.y; }
                    *(float2*)(C + o) = make_float2(v0, v1);
                } else if (mode == 1) {
                    split_store(H0, L0, prow*ldh0 + col, v0, v1);
                } else {
                    if (col < nq128)
                        split_store(H0, L0, prow*DM_ + col, v0, v1);
                    else if (col < nqk128)
                        split_store(H1, L1, prow*DM_ + (col - nq128), v0, v1);
                    else
                        *(float2*)(C + (size_t)row*ldc + (col - nqk128)) = make_float2(v0, v1);
                }
            }
        }
    }
}

// ---------------- prep ----------------
__global__ void k_sea(const float* __restrict__ xe, float* __restrict__ sea) {
    int i = blockIdx.x * blockDim.x + threadIdx.x;
    if (i >= B_*LE_*NC_) return;
    int c = i % NC_;
    int t = (i / NC_) % LE_;
    int b = i / (NC_*LE_);
    float s = 0.f;
    #pragma unroll
    for (int j = -12; j <= 12; j++) {
        int tt = t + j; tt = tt < 0 ? 0 : (tt >= LE_ ? LE_-1 : tt);
        s += xe[((size_t)b*LE_ + tt)*NC_ + c];
    }
    sea[i] = xe[i] - s * (1.0f/25.0f);
}

__global__ void k_meanc(const float* __restrict__ xe, float* __restrict__ mb) {
    int b = blockIdx.x, tid = threadIdx.x;
    __shared__ float red[7][32];
    if (tid < 224) {
        int c = tid % NC_, slot = tid / NC_;
        float s = 0.f;
        for (int t = slot; t < LE_; t += 32) s += xe[((size_t)b*LE_ + t)*NC_ + c];
        red[c][slot] = s;
    }
    __syncthreads();
    if (tid < NC_) {
        float s = 0.f;
        #pragma unroll
        for (int j = 0; j < 32; j++) s += red[tid][j];
        mb[b*NC_ + tid] = s * (1.0f/LE_);
    }
}

// ---------------- embeds v2: smem-cached weights, 32-t chunks -------------
__global__ void k_embed_enc2(const float* __restrict__ xe, const float* __restrict__ mk,
                             const float* __restrict__ Wemb, const float* __restrict__ Wm,
                             float* __restrict__ out, bf* __restrict__ H, bf* __restrict__ Lo) {
    int tc = blockIdx.x, b = blockIdx.y, dh = blockIdx.z;
    int tid = threadIdx.x;
    int d = dh*256 + tid;
    __shared__ float sw[25][256];
    __shared__ float sx[34][NC_];
    __shared__ float sm[32][NM_];
    for (int i = tid; i < 21*256; i += 256) {
        int j = i >> 8, dd = i & 255;
        sw[j][dd] = Wemb[(size_t)j*DM_ + dh*256 + dd];
    }
    for (int i = tid; i < 4*256; i += 256) {
        int m = i >> 8, dd = i & 255;
        sw[21+m][dd] = Wm[(size_t)m*DM_ + dh*256 + dd];
    }
    int t0 = tc*32;
    for (int i = tid; i < 34*NC_; i += 256) {
        int rr = i / NC_, c = i % NC_;
        int r = (t0 - 1 + rr + LE_) % LE_;
        sx[rr][c] = xe[((size_t)b*LE_ + r)*NC_ + c];
    }
    for (int i = tid; i < 32*NM_; i += 256) {
        int rr = i / NM_, m = i % NM_;
        sm[rr][m] = mk[((size_t)b*LE_ + t0 + rr)*NM_ + m];
    }
    __syncthreads();
    for (int tt = 0; tt < 32; tt++) {
        float acc = 0.f;
        #pragma unroll
        for (int j = 0; j < 3; j++)
            #pragma unroll
            for (int c = 0; c < NC_; c++)
                acc += sx[tt + j][c] * sw[j*NC_ + c][tid];
        #pragma unroll
        for (int m = 0; m < NM_; m++) acc += sm[tt][m] * sw[21+m][tid];
        size_t o = ((size_t)b*LE_ + t0 + tt)*DM_ + d;
        out[o] = acc;
        bf h = __float2bfloat16(acc);
        H[o] = h; Lo[o] = __float2bfloat16(acc - __bfloat162float(h));
    }
}

__global__ void k_embed_dec2(const float* __restrict__ sea, const float* __restrict__ mk_enc,
                             const float* __restrict__ mk_dec,
                             const float* __restrict__ Wemb, const float* __restrict__ Wm,
                             float* __restrict__ out, bf* __restrict__ H, bf* __restrict__ Lo) {
    int tc = blockIdx.x, b = blockIdx.y, dh = blockIdx.z;
    int tid = threadIdx.x;
    int d = dh*256 + tid;
    __shared__ float sw[25][256];
    __shared__ float sx[34][NC_];
    __shared__ float sm[32][NM_];
    for (int i = tid; i < 21*256; i += 256) {
        int j = i >> 8, dd = i & 255;
        sw[j][dd] = Wemb[(size_t)j*DM_ + dh*256 + dd];
    }
    for (int i = tid; i < 4*256; i += 256) {
        int m = i >> 8, dd = i & 255;
        sw[21+m][dd] = Wm[(size_t)m*DM_ + dh*256 + dd];
    }
    int t0 = tc*32;
    for (int i = tid; i < 34*NC_; i += 256) {
        int rr = i / NC_, c = i % NC_;
        int r = (t0 - 1 + rr + LD_) % LD_;
        sx[rr][c] = (r < LBL_) ? sea[((size_t)b*LE_ + LBL_ + r)*NC_ + c] : 0.f;
    }
    for (int i = tid; i < 32*NM_; i += 256) {
        int rr = i / NM_, m = i % NM_;
        int t = t0 + rr;
        float v = 0.f;
        if (t < LD_) {
            v = (t < LBL_) ? mk_enc[((size_t)b*LE_ + LBL_ + t)*NM_ + m]
                           : mk_dec[((size_t)b*PRED_ + (t - LBL_))*NM_ + m];
        }
        sm[rr][m] = v;
    }
    __syncthreads();
    for (int tt = 0; tt < 32; tt++) {
        int t = t0 + tt;
        if (t >= LD_) break;
        float acc = 0.f;
        #pragma unroll
        for (int j = 0; j < 3; j++)
            #pragma unroll
            for (int c = 0; c < NC_; c++)
                acc += sx[tt + j][c] * sw[j*NC_ + c][tid];
        #pragma unroll
        for (int m = 0; m < NM_; m++) acc += sm[tt][m] * sw[21+m][tid];
        size_t o = ((size_t)b*LD_ + t)*DM_ + d;
        out[o] = acc;
        bf h = __float2bfloat16(acc);
        H[o] = h; Lo[o] = __float2bfloat16(acc - __bfloat162float(h));
    }
}

// ---------------- pad-row zeroing ----------------
__global__ void k_padzero(bf* __restrict__ H, bf* __restrict__ L, int Lv){
    int span = LP_ - Lv;
    int n = B_*span*DM_;
    int i = blockIdx.x*256 + threadIdx.x;
    if (i >= n) return;
    int d = i % DM_;
    int rr = (i / DM_) % span;
    int b = i / (DM_*span);
    size_t o = ((size_t)b*LP_ + Lv + rr)*DM_ + d;
    H[o] = __float2bfloat16(0.f);
    L[o] = __float2bfloat16(0.f);
}

__global__ void k_zero(float* __restrict__ p, int n){
    int i = blockIdx.x*256 + threadIdx.x;
    if (i < n) p[i] = 0.f;
}

// ---------------- exact top-k + softmax (warp-shuffle) ----------------
__global__ void k_topk(const float* __restrict__ corr, int L, int KT,
                       int* __restrict__ delay, float* __restrict__ wgt) {
    int b = blockIdx.x, tid = threadIdx.x;
    int lane = tid & 31, wid = tid >> 5;
    __shared__ float vals[640];
    __shared__ float wv[8];
    __shared__ int wi[8];
    __shared__ float tv[32];
    __shared__ int tix[32];
    for (int i = tid; i < L; i += 256) vals[i] = corr[(size_t)b*L + i];
    __syncthreads();
    for (int kt = 0; kt < KT; kt++) {
        float bv = -FLT_MAX; int bi = 0x7fffffff;
        for (int i = tid; i < L; i += 256) {
            float v = vals[i];
            if (v > bv || (v == bv && i < bi)) { bv = v; bi = i; }
        }
        #pragma unroll
        for (int o = 16; o > 0; o >>= 1) {
            float ov = __shfl_down_sync(0xffffffffu, bv, o);
            int   oi = __shfl_down_sync(0xffffffffu, bi, o);
            if (ov > bv || (ov == bv && oi < bi)) { bv = ov; bi = oi; }
        }
        if (lane == 0) { wv[wid] = bv; wi[wid] = bi; }
        __syncthreads();
        if (wid == 0) {
            float v2 = (lane < 8) ? wv[lane] : -FLT_MAX;
            int   i2 = (lane < 8) ? wi[lane] : 0x7fffffff;
            #pragma unroll
            for (int o = 4; o > 0; o >>= 1) {
                float ov = __shfl_down_sync(0xffffffffu, v2, o);
                int   oi = __shfl_down_sync(0xffffffffu, i2, o);
                if (ov > v2 || (ov == v2 && oi < i2)) { v2 = ov; i2 = oi; }
            }
            if (lane == 0) { tv[kt] = v2; tix[kt] = i2; vals[i2] = -FLT_MAX; }
        }
        __syncthreads();
    }
    if (tid == 0) {
        float mx = tv[0], s = 0.f;
        float e[32];
        for (int i = 0; i < KT; i++) { e[i] = expf(tv[i] - mx); s += e[i]; }
        float inv = 1.0f / s;
        for (int i = 0; i < KT; i++) {
            wgt[b*32 + i] = e[i] * inv;
            delay[b*32 + i] = tix[i];
        }
    }
}

// ---------------- weighted circular gather (split out) ----------------
__global__ void k_agg(const float* __restrict__ V, int vld, const int* __restrict__ delay,
                      const float* __restrict__ wgt, bf* __restrict__ OH,
                      bf* __restrict__ OL, int L, int S, int KT, long long vbs) {
    int t = blockIdx.x, b = blockIdx.y, d = threadIdx.x;
    __shared__ int sd[32];
    __shared__ float sw[32];
    if (d < KT) { sd[d] = delay[b*32 + d]; sw[d] = wgt[b*32 + d]; }
    __syncthreads();
    float acc = 0.f;
    for (int i = 0; i < KT; i++) {
        int r = t + sd[i]; if (r >= L) r -= L;
        if (r < S) acc += sw[i] * V[(size_t)b*vbs + (size_t)r*vld + d];
    }
    size_t o = ((size_t)b*L + t)*DM_ + d;
    bf h = __float2bfloat16(acc);
    OH[o] = h; OL[o] = __float2bfloat16(acc - __bfloat162float(h));
}

// ---------------- series_decomp on single residual-summed array ----------
__global__ void k_add_decomp2(const float* __restrict__ R,
                              float* __restrict__ S, float* __restrict__ T,
                              bf* __restrict__ SH, bf* __restrict__ SL,
                              int L, int tmode) {
    int b = blockIdx.y, ch = blockIdx.x, d = threadIdx.x;
    int CH = (L + 7) / 8;
    int t0 = ch * CH, t1 = min(t0 + CH, L);
    if (t0 >= L) return;
    const size_t base = (size_t)b * L * DM_ + d;
    float w = 0.f;
    for (int j = -12; j <= 12; j++) {
        int tt = t0 + j; tt = tt < 0 ? 0 : (tt >= L ? L-1 : tt);
        w += R[base + (size_t)tt * DM_];
    }
    for (int t = t0; t < t1; t++) {
        size_t idx = base + (size_t)t * DM_;
        float cur = R[idx];
        float m = w * (1.0f/25.0f);
        float sv = cur - m;
        S[idx] = sv;
        bf h = __float2bfloat16(sv);
        SH[idx] = h; SL[idx] = __float2bfloat16(sv - __bfloat162float(h));
        if (tmode == 1) T[idx] = m;
        else if (tmode == 2) T[idx] += m;
        int ta = t + 13; ta = ta >= L ? L-1 : ta;
        int tr = t - 12; tr = tr < 0 ? 0 : tr;
        w += R[base + (size_t)ta * DM_] - R[base + (size_t)tr * DM_];
    }
}

// ---------------- layernorm ----------------
__global__ void k_ln(const float* __restrict__ X, const float* __restrict__ g,
                     const float* __restrict__ be, float* __restrict__ Y) {
    int row = blockIdx.x, tid = threadIdx.x;
    __shared__ float buf[DM_];
    __shared__ float red[256];
    __shared__ float smu, sinv;
    const float* xr = X + (size_t)row * DM_;
    float s = 0.f;
    for (int i = tid; i < DM_; i += 256) { float v = xr[i]; buf[i] = v; s += v; }
    red[tid] = s; __syncthreads();
    for (int st = 128; st > 0; st >>= 1) { if (tid < st) red[tid] += red[tid+st]; __syncthreads(); }
    if (tid == 0) smu = red[0] * (1.0f/DM_);
    __syncthreads();
    float mu = smu, s2 = 0.f;
    for (int i = tid; i < DM_; i += 256) { float dv = buf[i] - mu; s2 += dv*dv; }
    red[tid] = s2; __syncthreads();
    for (int st = 128; st > 0; st >>= 1) { if (tid < st) red[tid] += red[tid+st]; __syncthreads(); }
    if (tid == 0) sinv = rsqrtf(red[0] * (1.0f/DM_) + 1e-5f);
    __syncthreads();
    float inv = sinv;
    for (int i = tid; i < DM_; i += 256)
        Y[(size_t)row*DM_ + i] = (buf[i] - mu) * inv * g[i] + be[i];
}

__global__ void k_submean2(float* __restrict__ Y, bf* __restrict__ H, bf* __restrict__ L,
                           int Llen) {
    int b = blockIdx.x >> 3, c = blockIdx.x & 7;
    int dl = threadIdx.x & 63, tp = threadIdx.x >> 6;
    int d = c*64 + dl;
    size_t base = (size_t)b*Llen*DM_ + d;
    float s = 0.f;
    for (int t = tp; t < Llen; t += 4) s += Y[base + (size_t)t*DM_];
    __shared__ float red[4][64];
    red[tp][dl] = s; __syncthreads();
    if (tp == 0) red[0][dl] = (red[0][dl]+red[1][dl]+red[2][dl]+red[3][dl]) / (float)Llen;
    __syncthreads();
    float m = red[0][dl];
    for (int t = tp; t < Llen; t += 4) {
        size_t idx = base + (size_t)t*DM_;
        float v = Y[idx] - m;
        Y[idx] = v;
        if (H) {
            bf h = __float2bfloat16(v);
            H[idx] = h; L[idx] = __float2bfloat16(v - __bfloat162float(h));
        }
    }
}

// ---------------- final assembly ----------------
__global__ void k_final(const float* __restrict__ XLN, const float* __restrict__ TS,
                        const float* __restrict__ meanb, const float* __restrict__ Wt,
                        const float* __restrict__ Wp, const float* __restrict__ bp,
                        float* __restrict__ out) {
    int p = blockIdx.x, b = blockIdx.y, tid = threadIdx.x;
    int t = LBL_ + p;
    int r0 = (t - 1 + LD_) % LD_;
    int r2 = (t + 1) % LD_;
    float acc[NC_];
    #pragma unroll
    for (int c = 0; c < NC_; c++) acc[c] = 0.f;
    for (int d = tid; d < DM_; d += 256) {
        float xv  = XLN[((size_t)b*LD_ + t )*DM_ + d];
        float tv0 = TS [((size_t)b*LD_ + r0)*DM_ + d];
        float tv1 = TS [((size_t)b*LD_ + t )*DM_ + d];
        float tv2 = TS [((size_t)b*LD_ + r2)*DM_ + d];
        #pragma unroll
        for (int c = 0; c < NC_; c++) {
            acc[c] += xv  * Wp[(size_t)d*NC_ + c]
                    + tv0 * Wt[((size_t)0*DM_ + d)*NC_ + c]
                    + tv1 * Wt[((size_t)1*DM_ + d)*NC_ + c]
                    + tv2 * Wt[((size_t)2*DM_ + d)*NC_ + c];
        }
    }
    __shared__ float red[256];
    for (int c = 0; c < NC_; c++) {
        red[tid] = acc[c]; __syncthreads();
        for (int st = 128; st > 0; st >>= 1) { if (tid < st) red[tid] += red[tid+st]; __syncthreads(); }
        if (tid == 0)
            out[((size_t)b*PRED_ + p)*NC_ + c] = red[0] + meanb[b*NC_ + c] + bp[c];
        __syncthreads();
    }
}

// ================= host orchestration =================
static bf *ABH, *ABL, *QBH, *QBL, *KBH, *KBL, *HBH, *HBL, *WBH, *WBL;

extern "C" void kernel_launch(void* const* d_in, const int* in_sizes, int n_in,
                              void* d_out, int out_size) {
    const float* x_enc      = (const float*)d_in[0];
    const float* x_mark_enc = (const float*)d_in[1];
    const float* x_mark_dec = (const float*)d_in[3];
    const float* W_enc_emb  = (const float*)d_in[4];
    const float* W_mark_enc = (const float*)d_in[5];
    const float* W_dec_emb  = (const float*)d_in[6];
    const float* W_mark_dec = (const float*)d_in[7];
    const float* eW_attn    = (const float*)d_in[8];
    const float* eb_attn    = (const float*)d_in[9];
    const float* eW1        = (const float*)d_in[10];
    const float* eW2        = (const float*)d_in[11];
    const float* eg         = (const float*)d_in[12];
    const float* ebeta      = (const float*)d_in[13];
    const float* sW         = (const float*)d_in[14];
    const float* sb         = (const float*)d_in[15];
    const float* cW         = (const float*)d_in[16];
    const float* cb         = (const float*)d_in[17];
    const float* dW1        = (const float*)d_in[18];
    const float* dW2        = (const float*)d_in[19];
    const float* W_trend    = (const float*)d_in[20];
    const float* dg         = (const float*)d_in[21];
    const float* dbeta      = (const float*)d_in[22];
    const float* Wproj      = (const float*)d_in[23];
    const float* bproj      = (const float*)d_in[24];
    float* out = (float*)d_out;

    cudaFuncSetAttribute(k_mma, cudaFuncAttributeMaxDynamicSharedMemorySize, SMEM_SZ);

    float* ws = nullptr;
    cudaGetSymbolAddress((void**)&ws, g_ws);
    int* dly = nullptr;
    cudaGetSymbolAddress((void**)&dly, g_delay);
    cudaGetSymbolAddress((void**)&ABH, g_abh);
    cudaGetSymbolAddress((void**)&ABL, g_abl);
    cudaGetSymbolAddress((void**)&QBH, g_qbh);
    cudaGetSymbolAddress((void**)&QBL, g_qbl);
    cudaGetSymbolAddress((void**)&KBH, g_kbh);
    cudaGetSymbolAddress((void**)&KBL, g_kbl);
    cudaGetSymbolAddress((void**)&HBH, g_hbh);
    cudaGetSymbolAddress((void**)&HBL, g_hbl);
    cudaGetSymbolAddress((void**)&WBH, g_wbh);
    cudaGetSymbolAddress((void**)&WBL, g_wbl);

    float* XE   = ws + O_XE;
    float* XA   = ws + O_XA;
    float* XD   = ws + O_XD;
    float* Qb   = ws + O_Q;
    float* Vb   = ws + O_V;
    float* Tb   = ws + O_T;
    float* CORR = ws + O_CORR;
    float* ENC  = ws + O_ENC;
    float* TS   = ws + O_TS;
    float* SEA  = ws + O_SEA;
    float* MEANB= ws + O_MEAN;
    float* WGT  = ws + O_WGT;

    // ---- fused weight transpose+split ----
    k_cvtT_all<<<10240, dim3(32,8)>>>(eW_attn, eW1, eW2, sW, cW, dW1, dW2, WBH, WBL);

    // ---- prep ----
    k_sea<<<(B_*LE_*NC_ + 255)/256, 256>>>(x_enc, SEA);
    k_meanc<<<B_, 256>>>(x_enc, MEANB);
    k_embed_enc2<<<dim3(LE_/32, B_, 2), 256>>>(x_enc, x_mark_enc, W_enc_emb, W_mark_enc, XE, ABH, ABL);

    // ---- encoder: 2 layers ----
    float* x = XE;
    for (int l = 0; l < 2; l++) {
        const float* bb = eb_attn + (size_t)l*4*DM_;
        size_t wa = OW_EATT + (size_t)l*4*DM_*DM_;
        k_mma<<<dim3(12,128,1), 256, SMEM_SZ>>>(ABH, ABL, DM_, WBH+wa, WBL+wa, DM_,
            DM_, B_*LE_, 1536, 0, 0, 0,
            2, Vb, DM_, QBH, QBL, 0, KBH, KBL, LE_, LE_, 4, 4, nullptr, bb, 0);
        k_zero<<<(B_*LE_ + 255)/256, 256>>>(CORR, B_*LE_);
        k_mma<<<dim3(4,4,B_), 256, SMEM_SZ>>>(QBH, QBL, DM_, KBH, KBL, DM_,
            DM_, LE_, LE_, (long long)LE_*DM_, (long long)LE_*DM_, (long long)LE_,
            4, CORR, 0, nullptr, nullptr, 0, nullptr, nullptr, LE_, LE_, 0, 0, nullptr, nullptr, 0);
        k_topk<<<B_, 256>>>(CORR, LE_, KT_E, dly, WGT);
        k_agg<<<dim3(LE_, B_), DM_>>>(Vb, DM_, dly, WGT, ABH, ABL,
                                      LE_, LE_, KT_E, (long long)LE_*DM_);
        k_mma<<<dim3(4,128,1), 256, SMEM_SZ>>>(ABH, ABL, DM_,
            WBH+wa+3*(size_t)DM_*DM_, WBL+wa+3*(size_t)DM_*DM_, DM_,
            DM_, B_*LE_, DM_, 0, 0, 0,
            0, Tb, DM_, nullptr, nullptr, 0, nullptr, nullptr, LE_, LE_, 0, 0, x, bb+3*DM_, 0);
        float* nx = (x == XE) ? XA : XE;
        k_add_decomp2<<<dim3(8, B_), DM_>>>(Tb, nx, nullptr, ABH, ABL, LE_, 0);
        x = nx;
        k_mma<<<dim3(16,128,1), 256, SMEM_SZ>>>(ABH, ABL, DM_,
            WBH+OW_EW1+(size_t)l*DM_*DFF_, WBL+OW_EW1+(size_t)l*DM_*DFF_, DM_,
            DM_, B_*LE_, DFF_, 0, 0, 0,
            1, nullptr, 0, HBH, HBL, DFF_, nullptr, nullptr, LE_, LE_, 0, 0, nullptr, nullptr, 1);
        k_mma<<<dim3(4,128,1), 256, SMEM_SZ>>>(HBH, HBL, DFF_,
            WBH+OW_EW2+(size_t)l*DFF_*DM_, WBL+OW_EW2+(size_t)l*DFF_*DM_, DFF_,
            DFF_, B_*LE_, DM_, 0, 0, 0,
            0, Tb, DM_, nullptr, nullptr, 0, nullptr, nullptr, LE_, LE_, 0, 0, x, nullptr, 0);
        nx = (x == XE) ? XA : XE;
        k_add_decomp2<<<dim3(8, B_), DM_>>>(Tb, nx, nullptr, ABH, ABL, LE_, 0);
        x = nx;
    }
    k_ln<<<B_*LE_, 256>>>(x, eg, ebeta, ENC);
    k_submean2<<<B_*8, 256>>>(ENC, HBH, HBL, LE_);   // ENC split cached in HBH/HBL

    // ---- decoder ----
    k_embed_dec2<<<dim3((LD_+31)/32, B_, 2), 256>>>(SEA, x_mark_enc, x_mark_dec,
                                                    W_dec_emb, W_mark_dec, XD, ABH, ABL);
    float* xd = XD;

    // zero pad rows [592,640) of QB/KB (dirtied by encoder usage)
    {
        int n = B_*(LP_-LD_)*DM_;
        k_padzero<<<(n+255)/256, 256>>>(QBH, QBL, LD_);
        k_padzero<<<(n+255)/256, 256>>>(KBH, KBL, LD_);
    }

    // self attention
    k_mma<<<dim3(12,148,1), 256, SMEM_SZ>>>(ABH, ABL, DM_, WBH+OW_SW, WBL+OW_SW, DM_,
        DM_, B_*LD_, 1536, 0, 0, 0,
        2, Vb, DM_, QBH, QBL, 0, KBH, KBL, LD_, LP_, 4, 4, nullptr, sb, 0);
    k_zero<<<(B_*LD_ + 255)/256, 256>>>(CORR, B_*LD_);
    k_mma<<<dim3(5,5,B_), 256, SMEM_SZ>>>(QBH, QBL, DM_, KBH, KBL, DM_,
        DM_, LD_, LD_, (long long)LP_*DM_, (long long)LP_*DM_, (long long)LD_,
        4, CORR, 0, nullptr, nullptr, 0, nullptr, nullptr, LD_, LD_, 0, 0, nullptr, nullptr, 0);
    k_topk<<<B_, 256>>>(CORR, LD_, KT_D, dly, WGT);
    k_agg<<<dim3(LD_, B_), DM_>>>(Vb, DM_, dly, WGT, ABH, ABL,
                                  LD_, LD_, KT_D, (long long)LD_*DM_);
    k_mma<<<dim3(4,148,1), 256, SMEM_SZ>>>(ABH, ABL, DM_,
        WBH+OW_SW+3*(size_t)DM_*DM_, WBL+OW_SW+3*(size_t)DM_*DM_, DM_,
        DM_, B_*LD_, DM_, 0, 0, 0,
        0, Tb, DM_, nullptr, nullptr, 0, nullptr, nullptr, LD_, LD_, 0, 0, xd, sb+3*DM_, 0);
    k_add_decomp2<<<dim3(8, B_), DM_>>>(Tb, XA, TS, ABH, ABL, LD_, 1);
    xd = XA;

    // cross attention: Q from x (padded split), K/V merged from ENC split
    k_mma<<<dim3(4,148,1), 256, SMEM_SZ>>>(ABH, ABL, DM_, WBH+OW_CW, WBL+OW_CW, DM_,
        DM_, B_*LD_, DM_, 0, 0, 0,
        1, nullptr, 0, QBH, QBL, DM_, nullptr, nullptr, LD_, LP_, 0, 0, nullptr, cb, 0);
    {
        int n = B_*(LP_-LE_)*DM_;
        k_padzero<<<(n+255)/256, 256>>>(KBH, KBL, LE_);
    }
    k_mma<<<dim3(8,128,1), 256, SMEM_SZ>>>(HBH, HBL, DM_,
        WBH+OW_CW+(size_t)DM_*DM_, WBL+OW_CW+(size_t)DM_*DM_, DM_,
        DM_, B_*LE_, 1024, 0, 0, 0,
        3, Vb, DM_, nullptr, nullptr, 0, KBH, KBL, LE_, LP_, 0, 4, nullptr, cb+DM_, 0);
    k_zero<<<(B_*LD_ + 255)/256, 256>>>(CORR, B_*LD_);
    k_mma<<<dim3(5,5,B_), 256, SMEM_SZ>>>(QBH, QBL, DM_, KBH, KBL, DM_,
        DM_, LD_, LD_, (long long)LP_*DM_, (long long)LP_*DM_, (long long)LD_,
        4, CORR, 0, nullptr, nullptr, 0, nullptr, nullptr, LD_, LD_, 0, 0, nullptr, nullptr, 0);
    k_topk<<<B_, 256>>>(CORR, LD_, KT_D, dly, WGT);
    k_agg<<<dim3(LD_, B_), DM_>>>(Vb, DM_, dly, WGT, ABH, ABL,
                                  LD_, LE_, KT_D, (long long)LE_*DM_);
    k_mma<<<dim3(4,148,1), 256, SMEM_SZ>>>(ABH, ABL, DM_,
        WBH+OW_CW+3*(size_t)DM_*DM_, WBL+OW_CW+3*(size_t)DM_*DM_, DM_,
        DM_, B_*LD_, DM_, 0, 0, 0,
        0, Tb, DM_, nullptr, nullptr, 0, nullptr, nullptr, LD_, LD_, 0, 0, xd, cb+3*DM_, 0);
    k_add_decomp2<<<dim3(8, B_), DM_>>>(Tb, XD, TS, ABH, ABL, LD_, 2);
    xd = XD;

    // FFN
    k_mma<<<dim3(16,148,1), 256, SMEM_SZ>>>(ABH, ABL, DM_,
        WBH+OW_DW1, WBL+OW_DW1, DM_,
        DM_, B_*LD_, DFF_, 0, 0, 0,
        1, nullptr, 0, HBH, HBL, DFF_, nullptr, nullptr, LD_, LD_, 0, 0, nullptr, nullptr, 1);
    k_mma<<<dim3(4,148,1), 256, SMEM_SZ>>>(HBH, HBL, DFF_,
        WBH+OW_DW2, WBL+OW_DW2, DFF_,
        DFF_, B_*LD_, DM_, 0, 0, 0,
        0, Tb, DM_, nullptr, nullptr, 0, nullptr, nullptr, LD_, LD_, 0, 0, xd, nullptr, 0);
    k_add_decomp2<<<dim3(8, B_), DM_>>>(Tb, XA, TS, ABH, ABL, LD_, 2);
    xd = XA;

    // final layernorm + output assembly
    k_ln<<<B_*LD_, 256>>>(xd, dg, dbeta, Qb);
    k_submean2<<<B_*8, 256>>>(Qb, nullptr, nullptr, LD_);
    k_final<<<dim3(PRED_, B_), 256>>>(Qb, TS, MEANB, W_trend, Wproj, bproj, out);
}

// round 11
// speedup vs baseline: 1.0255x; 1.0255x over previous
#include <cuda_runtime.h>
#include <cuda_bf16.h>
#include <math.h>
#include <float.h>
#include <stdint.h>

typedef __nv_bfloat16 bf;

// ---------------- problem constants ----------------
#define B_    32
#define LE_   512
#define LD_   592
#define LP_   640
#define DM_   512
#define DFF_  2048
#define NC_   7
#define NM_   4
#define LBL_  256
#define PRED_ 336
#define KT_E  18
#define KT_D  19

// ---------------- fp32 workspace ----------------
#define SZ_XE  ((size_t)B_*LE_*DM_)
#define SZ_XD  ((size_t)B_*LD_*DM_)
#define SZ_G   ((size_t)B_*LD_*LD_)

#define O_XE   ((size_t)0)
#define O_XA   (O_XE + SZ_XE)
#define O_XD   (O_XA + SZ_XD)
#define O_Q    (O_XD + SZ_XD)
#define O_V    (O_Q  + SZ_XD)
#define O_T    (O_V  + SZ_XD)
#define O_G    (O_T  + SZ_XD)
#define O_CORR (O_G  + SZ_G)
#define O_ENC  (O_CORR + (size_t)B_*LD_)
#define O_TS   (O_ENC + SZ_XE)
#define O_SEA  (O_TS + SZ_XD)
#define O_MEAN (O_SEA + (size_t)B_*LE_*NC_)
#define O_WGT  (O_MEAN + (size_t)B_*NC_)
#define WS_TOTAL (O_WGT + (size_t)B_*32)

__device__ __align__(256) float g_ws[WS_TOTAL];
__device__ int g_delay[B_*32];

// ---------------- bf16 split workspace ----------------
#define SZ_AB  ((size_t)B_*LP_*DM_)
#define SZ_QB  ((size_t)B_*LP_*DM_)
#define SZ_KB  ((size_t)B_*LP_*DM_)
#define SZ_HB  ((size_t)B_*LD_*DFF_)
#define OW_EATT ((size_t)0)
#define OW_EW1  ((size_t)2097152)
#define OW_EW2  ((size_t)4194304)
#define OW_SW   ((size_t)6291456)
#define OW_CW   ((size_t)7340032)
#define OW_DW1  ((size_t)8388608)
#define OW_DW2  ((size_t)9437184)
#define SZ_WB   ((size_t)10485760)

__device__ __align__(256) bf g_abh[SZ_AB];
__device__ __align__(256) bf g_abl[SZ_AB];
__device__ __align__(256) bf g_qbh[SZ_QB];
__device__ __align__(256) bf g_qbl[SZ_QB];
__device__ __align__(256) bf g_kbh[SZ_KB];
__device__ __align__(256) bf g_kbl[SZ_KB];
__device__ __align__(256) bf g_hbh[SZ_HB];
__device__ __align__(256) bf g_hbl[SZ_HB];
__device__ __align__(256) bf g_wbh[SZ_WB];
__device__ __align__(256) bf g_wbl[SZ_WB];

// ---------------- helpers ----------------
__device__ __forceinline__ float gelu_exact(float v) {
    return 0.5f * v * (1.0f + erff(v * 0.70710678118654752440f));
}
__device__ __forceinline__ uint32_t s2u(const void* p){
    uint32_t a;
    asm("{ .reg .u64 t; cvta.to.shared.u64 t, %1; cvt.u32.u64 %0, t; }":"=r"(a):"l"(p));
    return a;
}
#define SWZ(o) ((o) ^ (((o)>>3)&0x70))

#define LDSM4(r, ad) \
    asm volatile("ldmatrix.sync.aligned.m8n8.x4.shared.b16 {%0,%1,%2,%3}, [%4];" \
        : "=r"((r)[0]), "=r"((r)[1]), "=r"((r)[2]), "=r"((r)[3]) : "r"(ad))

#define MMA16816(d, a, b0, b1) \
    asm volatile("mma.sync.aligned.m16n8k16.row.col.f32.bf16.bf16.f32 " \
        "{%0,%1,%2,%3}, {%4,%5,%6,%7}, {%8,%9}, {%0,%1,%2,%3};" \
        : "+f"((d)[0]), "+f"((d)[1]), "+f"((d)[2]), "+f"((d)[3]) \
        : "r"((a)[0]), "r"((a)[1]), "r"((a)[2]), "r"((a)[3]), "r"(b0), "r"(b1))

__device__ __forceinline__ void split_store(bf* H, bf* L, size_t o, float v0, float v1){
    bf h0 = __float2bfloat16(v0), h1 = __float2bfloat16(v1);
    bf l0 = __float2bfloat16(v0 - __bfloat162float(h0));
    bf l1 = __float2bfloat16(v1 - __bfloat162float(h1));
    *(__nv_bfloat162*)(H + o) = __nv_bfloat162(h0, h1);
    *(__nv_bfloat162*)(L + o) = __nv_bfloat162(l0, l1);
}

// ---------------- fused weight transpose+split ----------------
__global__ void k_cvtT_all(const float* __restrict__ eatt, const float* __restrict__ e1,
                           const float* __restrict__ e2, const float* __restrict__ sw,
                           const float* __restrict__ cw, const float* __restrict__ d1,
                           const float* __restrict__ d2,
                           bf* __restrict__ WH, bf* __restrict__ WL){
    __shared__ float t[32][33];
    int blk = blockIdx.x;
    const float* src; size_t dstoff; int K, N, mi, tt;
    if (blk < 2048)       { src=eatt; dstoff=OW_EATT; K=512; N=512;  mi=blk/256;        tt=blk%256; }
    else if (blk < 4096)  { src=e1;   dstoff=OW_EW1;  K=512; N=2048; mi=(blk-2048)/1024; tt=(blk-2048)%1024; }
    else if (blk < 6144)  { src=e2;   dstoff=OW_EW2;  K=2048;N=512;  mi=(blk-4096)/1024; tt=(blk-4096)%1024; }
    else if (blk < 7168)  { src=sw;   dstoff=OW_SW;   K=512; N=512;  mi=(blk-6144)/256;  tt=(blk-6144)%256; }
    else if (blk < 8192)  { src=cw;   dstoff=OW_CW;   K=512; N=512;  mi=(blk-7168)/256;  tt=(blk-7168)%256; }
    else if (blk < 9216)  { src=d1;   dstoff=OW_DW1;  K=512; N=2048; mi=0;               tt=blk-8192; }
    else                  { src=d2;   dstoff=OW_DW2;  K=2048;N=512;  mi=0;               tt=blk-9216; }
    int tn = N/32;
    int n0 = (tt % tn)*32, k0 = (tt / tn)*32;
    const float* W = src + (size_t)mi*K*N;
    bf* TH = WH + dstoff + (size_t)mi*K*N;
    bf* TL = WL + dstoff + (size_t)mi*K*N;
    int tx = threadIdx.x, ty = threadIdx.y;
    #pragma unroll
    for (int i = 0; i < 32; i += 8)
        t[ty+i][tx] = W[(size_t)(k0+ty+i)*N + n0 + tx];
    __syncthreads();
    #pragma unroll
    for (int i = 0; i < 32; i += 8) {
        float x = t[tx][ty+i];
        bf h = __float2bfloat16(x);
        size_t o = (size_t)(n0+ty+i)*K + k0 + tx;
        TH[o] = h; TL[o] = __float2bfloat16(x - __bfloat162float(h));
    }
}

// ---------------- bf16x3 mma.sync GEMM, routed epilogue ----------------
// mode 0: C fp32 dense (+ optional RES residual add), batched via cB
// mode 1: split H0/L0, padded rows (Lv->Lp), ld ldh0
// mode 2/3: col-routed QKV / KV (split padded + fp32 tail)
#define SMEM_SZ 131072

__device__ __forceinline__ void ldchunk(uint32_t st,
    const bf* __restrict__ A_h, const bf* __restrict__ A_l, int lda,
    const bf* __restrict__ B_h, const bf* __restrict__ B_l, int ldb,
    int k0, int tid)
{
    const bf* srcs[4] = {A_h, A_l, B_h, B_l};
    const int lds[4] = {lda, lda, ldb, ldb};
    #pragma unroll
    for (int t = 0; t < 4; t++) {
        #pragma unroll
        for (int i = 0; i < 4; i++) {
            int idx = i*256 + tid;
            int row = idx >> 3, c16 = idx & 7;
            uint32_t dst = st + t*16384 + SWZ(row*128 + c16*16);
            const bf* src = srcs[t] + (size_t)row*lds[t] + k0 + c16*8;
            asm volatile("cp.async.cg.shared.global [%0], [%1], 16;\n"::"r"(dst),"l"(src));
        }
    }
    asm volatile("cp.async.commit_group;\n":::"memory");
}

__global__ void __launch_bounds__(256,1) k_mma(
    const bf* __restrict__ Ah, const bf* __restrict__ Al, int lda,
    const bf* __restrict__ Bh, const bf* __restrict__ Bl, int ldb,
    int K, int rowsV, int colsV,
    long long aB, long long bB, long long cB,
    int mode, float* __restrict__ C, int ldc,
    bf* __restrict__ H0, bf* __restrict__ L0, int ldh0,
    bf* __restrict__ H1, bf* __restrict__ L1,
    int Lv, int Lp, int nq, int nk,
    const float* __restrict__ RES, const float* __restrict__ bias, int act)
{
    extern __shared__ char smem[];
    uint32_t sb0 = s2u(smem);
    const int tid = threadIdx.x, lane = tid & 31, wid = tid >> 5;
    const int bn = blockIdx.x, bm = blockIdx.y, bz = blockIdx.z;
    const bf* Ah2 = Ah + (size_t)bz*aB + (size_t)bm*128*lda;
    const bf* Al2 = Al + (size_t)bz*aB + (size_t)bm*128*lda;
    const bf* Bh2 = Bh + (size_t)bz*bB + (size_t)bn*128*ldb;
    const bf* Bl2 = Bl + (size_t)bz*bB + (size_t)bn*128*ldb;
    if (C) C += (size_t)bz*cB;

    float acc[4][4][4];
    #pragma unroll
    for (int i = 0; i < 4; i++)
        #pragma unroll
        for (int j = 0; j < 4; j++)
            #pragma unroll
            for (int q = 0; q < 4; q++) acc[i][j][q] = 0.f;

    const int KC = K >> 6;
    const int m0 = (wid & 1) << 6, n0 = (wid >> 1) << 5;

    ldchunk(sb0, Ah2, Al2, lda, Bh2, Bl2, ldb, 0, tid);

    for (int c = 0; c < KC; c++) {
        uint32_t st = sb0 + (uint32_t)(c & 1) * 65536u;
        if (c+1 < KC) {
            ldchunk(sb0 + (uint32_t)((c+1) & 1) * 65536u,
                    Ah2, Al2, lda, Bh2, Bl2, ldb, (c+1)*64, tid);
            asm volatile("cp.async.wait_group 1;\n":::"memory");
        } else {
            asm volatile("cp.async.wait_group 0;\n":::"memory");
        }
        __syncthreads();

        #pragma unroll
        for (int kk = 0; kk < 4; kk++) {
            uint32_t afh[4][4], afl[4][4], bfh[2][4], bfl[2][4];
            #pragma unroll
            for (int mt = 0; mt < 4; mt++) {
                int m = m0 + mt*16 + (lane & 15);
                int kb = kk*32 + ((lane >> 4) << 4);
                uint32_t off = SWZ(m*128 + kb);
                LDSM4(afh[mt], st + off);
                LDSM4(afl[mt], st + 16384u + off);
            }
            #pragma unroll
            for (int nt2 = 0; nt2 < 2; nt2++) {
                int g = lane >> 3;
                int n = n0 + nt2*16 + ((g >> 1) << 3) + (lane & 7);
                int kb = kk*32 + ((g & 1) << 4);
                uint32_t off = SWZ(n*128 + kb);
                LDSM4(bfh[nt2], st + 32768u + off);
                LDSM4(bfl[nt2], st + 49152u + off);
            }
            #pragma unroll
            for (int mt = 0; mt < 4; mt++)
                #pragma unroll
                for (int nt = 0; nt < 4; nt++)
                    MMA16816(acc[mt][nt], afh[mt],
                             bfh[nt>>1][(nt&1)*2], bfh[nt>>1][(nt&1)*2+1]);
            #pragma unroll
            for (int mt = 0; mt < 4; mt++)
                #pragma unroll
                for (int nt = 0; nt < 4; nt++)
                    MMA16816(acc[mt][nt], afh[mt],
                             bfl[nt>>1][(nt&1)*2], bfl[nt>>1][(nt&1)*2+1]);
            #pragma unroll
            for (int mt = 0; mt < 4; mt++)
                #pragma unroll
                for (int nt = 0; nt < 4; nt++)
                    MMA16816(acc[mt][nt], afl[mt],
                             bfh[nt>>1][(nt&1)*2], bfh[nt>>1][(nt&1)*2+1]);
        }
        __syncthreads();
    }

    const int gid = lane >> 2, tig = lane & 3;
    const int nq128 = nq*128, nqk128 = (nq+nk)*128;
    #pragma unroll
    for (int mt = 0; mt < 4; mt++) {
        #pragma unroll
        for (int h = 0; h < 2; h++) {
            int row = bm*128 + m0 + mt*16 + gid + h*8;
            if (row >= rowsV) continue;
            int bq = row / Lv, rr = row - bq*Lv;
            size_t prow = (size_t)bq*Lp + rr;
            #pragma unroll
            for (int nt = 0; nt < 4; nt++) {
                int col = bn*128 + n0 + nt*8 + tig*2;
                if (col >= colsV) continue;
                float v0 = acc[mt][nt][h*2+0];
                float v1 = acc[mt][nt][h*2+1];
                if (bias) { v0 += bias[col]; v1 += bias[col+1]; }
                if (act)  { v0 = gelu_exact(v0); v1 = gelu_exact(v1); }
                if (mode == 0) {
                    size_t o = (size_t)row*ldc + col;
                    if (RES) { float2 r2 = *(const float2*)(RES + o); v0 += r2.x; v1 += r2.y; }
                    *(float2*)(C + o) = make_float2(v0, v1);
                } else if (mode == 1) {
                    split_store(H0, L0, prow*ldh0 + col, v0, v1);
                } else {
                    if (col < nq128)
                        split_store(H0, L0, prow*DM_ + col, v0, v1);
                    else if (col < nqk128)
                        split_store(H1, L1, prow*DM_ + (col - nq128), v0, v1);
                    else
                        *(float2*)(C + (size_t)row*ldc + (col - nqk128)) = make_float2(v0, v1);
                }
            }
        }
    }
}

// ---------------- prep ----------------
__global__ void k_sea(const float* __restrict__ xe, float* __restrict__ sea) {
    int i = blockIdx.x * blockDim.x + threadIdx.x;
    if (i >= B_*LE_*NC_) return;
    int c = i % NC_;
    int t = (i / NC_) % LE_;
    int b = i / (NC_*LE_);
    float s = 0.f;
    #pragma unroll
    for (int j = -12; j <= 12; j++) {
        int tt = t + j; tt = tt < 0 ? 0 : (tt >= LE_ ? LE_-1 : tt);
        s += xe[((size_t)b*LE_ + tt)*NC_ + c];
    }
    sea[i] = xe[i] - s * (1.0f/25.0f);
}

__global__ void k_meanc(const float* __restrict__ xe, float* __restrict__ mb) {
    int b = blockIdx.x, tid = threadIdx.x;
    __shared__ float red[7][32];
    if (tid < 224) {
        int c = tid % NC_, slot = tid / NC_;
        float s = 0.f;
        for (int t = slot; t < LE_; t += 32) s += xe[((size_t)b*LE_ + t)*NC_ + c];
        red[c][slot] = s;
    }
    __syncthreads();
    if (tid < NC_) {
        float s = 0.f;
        #pragma unroll
        for (int j = 0; j < 32; j++) s += red[tid][j];
        mb[b*NC_ + tid] = s * (1.0f/LE_);
    }
}

// ---------------- embeds v2: smem-cached weights, 32-t chunks -------------
__global__ void k_embed_enc2(const float* __restrict__ xe, const float* __restrict__ mk,
                             const float* __restrict__ Wemb, const float* __restrict__ Wm,
                             float* __restrict__ out, bf* __restrict__ H, bf* __restrict__ Lo) {
    int tc = blockIdx.x, b = blockIdx.y, dh = blockIdx.z;
    int tid = threadIdx.x;
    int d = dh*256 + tid;
    __shared__ float sw[25][256];
    __shared__ float sx[34][NC_];
    __shared__ float sm[32][NM_];
    for (int i = tid; i < 21*256; i += 256) {
        int j = i >> 8, dd = i & 255;
        sw[j][dd] = Wemb[(size_t)j*DM_ + dh*256 + dd];
    }
    for (int i = tid; i < 4*256; i += 256) {
        int m = i >> 8, dd = i & 255;
        sw[21+m][dd] = Wm[(size_t)m*DM_ + dh*256 + dd];
    }
    int t0 = tc*32;
    for (int i = tid; i < 34*NC_; i += 256) {
        int rr = i / NC_, c = i % NC_;
        int r = (t0 - 1 + rr + LE_) % LE_;
        sx[rr][c] = xe[((size_t)b*LE_ + r)*NC_ + c];
    }
    for (int i = tid; i < 32*NM_; i += 256) {
        int rr = i / NM_, m = i % NM_;
        sm[rr][m] = mk[((size_t)b*LE_ + t0 + rr)*NM_ + m];
    }
    __syncthreads();
    for (int tt = 0; tt < 32; tt++) {
        float acc = 0.f;
        #pragma unroll
        for (int j = 0; j < 3; j++)
            #pragma unroll
            for (int c = 0; c < NC_; c++)
                acc += sx[tt + j][c] * sw[j*NC_ + c][tid];
        #pragma unroll
        for (int m = 0; m < NM_; m++) acc += sm[tt][m] * sw[21+m][tid];
        size_t o = ((size_t)b*LE_ + t0 + tt)*DM_ + d;
        out[o] = acc;
        bf h = __float2bfloat16(acc);
        H[o] = h; Lo[o] = __float2bfloat16(acc - __bfloat162float(h));
    }
}

__global__ void k_embed_dec2(const float* __restrict__ sea, const float* __restrict__ mk_enc,
                             const float* __restrict__ mk_dec,
                             const float* __restrict__ Wemb, const float* __restrict__ Wm,
                             float* __restrict__ out, bf* __restrict__ H, bf* __restrict__ Lo) {
    int tc = blockIdx.x, b = blockIdx.y, dh = blockIdx.z;
    int tid = threadIdx.x;
    int d = dh*256 + tid;
    __shared__ float sw[25][256];
    __shared__ float sx[34][NC_];
    __shared__ float sm[32][NM_];
    for (int i = tid; i < 21*256; i += 256) {
        int j = i >> 8, dd = i & 255;
        sw[j][dd] = Wemb[(size_t)j*DM_ + dh*256 + dd];
    }
    for (int i = tid; i < 4*256; i += 256) {
        int m = i >> 8, dd = i & 255;
        sw[21+m][dd] = Wm[(size_t)m*DM_ + dh*256 + dd];
    }
    int t0 = tc*32;
    for (int i = tid; i < 34*NC_; i += 256) {
        int rr = i / NC_, c = i % NC_;
        int r = (t0 - 1 + rr + LD_) % LD_;
        sx[rr][c] = (r < LBL_) ? sea[((size_t)b*LE_ + LBL_ + r)*NC_ + c] : 0.f;
    }
    for (int i = tid; i < 32*NM_; i += 256) {
        int rr = i / NM_, m = i % NM_;
        int t = t0 + rr;
        float v = 0.f;
        if (t < LD_) {
            v = (t < LBL_) ? mk_enc[((size_t)b*LE_ + LBL_ + t)*NM_ + m]
                           : mk_dec[((size_t)b*PRED_ + (t - LBL_))*NM_ + m];
        }
        sm[rr][m] = v;
    }
    __syncthreads();
    for (int tt = 0; tt < 32; tt++) {
        int t = t0 + tt;
        if (t >= LD_) break;
        float acc = 0.f;
        #pragma unroll
        for (int j = 0; j < 3; j++)
            #pragma unroll
            for (int c = 0; c < NC_; c++)
                acc += sx[tt + j][c] * sw[j*NC_ + c][tid];
        #pragma unroll
        for (int m = 0; m < NM_; m++) acc += sm[tt][m] * sw[21+m][tid];
        size_t o = ((size_t)b*LD_ + t)*DM_ + d;
        out[o] = acc;
        bf h = __float2bfloat16(acc);
        H[o] = h; Lo[o] = __float2bfloat16(acc - __bfloat162float(h));
    }
}

// ---------------- pad-row zeroing ----------------
__global__ void k_padzero(bf* __restrict__ H, bf* __restrict__ L, int Lv){
    int span = LP_ - Lv;
    int n = B_*span*DM_;
    int i = blockIdx.x*256 + threadIdx.x;
    if (i >= n) return;
    int d = i % DM_;
    int rr = (i / DM_) % span;
    int b = i / (DM_*span);
    size_t o = ((size_t)b*LP_ + Lv + rr)*DM_ + d;
    H[o] = __float2bfloat16(0.f);
    L[o] = __float2bfloat16(0.f);
}

__global__ void k_zero(float* __restrict__ p, int n){
    int i = blockIdx.x*256 + threadIdx.x;
    if (i < n) p[i] = 0.f;
}

// ---------------- mean_corr: coalesced scatter ----------------
__global__ void k_corr2(const float* __restrict__ G, float* __restrict__ corr,
                        int L, int gbs) {
    int b = blockIdx.y, tid = threadIdx.x;
    int t0 = blockIdx.x * 16;
    __shared__ float cs[640];
    for (int i = tid; i < L; i += 256) cs[i] = 0.f;
    __syncthreads();
    const float* Gb = G + (size_t)b*gbs;
    int t1 = min(t0 + 16, L);
    for (int t = t0; t < t1; t++) {
        const float* row = Gb + (size_t)t*L;
        for (int j = tid; j < L; j += 256) {
            int tau = t - j; if (tau < 0) tau += L;
            atomicAdd(&cs[tau], row[j]);
        }
    }
    __syncthreads();
    for (int i = tid; i < L; i += 256)
        atomicAdd(&corr[(size_t)b*L + i], cs[i] * (1.0f/DM_));
}

// ---------------- exact top-k + softmax (warp-shuffle) ----------------
__global__ void k_topk(const float* __restrict__ corr, int L, int KT,
                       int* __restrict__ delay, float* __restrict__ wgt) {
    int b = blockIdx.x, tid = threadIdx.x;
    int lane = tid & 31, wid = tid >> 5;
    __shared__ float vals[640];
    __shared__ float wv[8];
    __shared__ int wi[8];
    __shared__ float tv[32];
    __shared__ int tix[32];
    for (int i = tid; i < L; i += 256) vals[i] = corr[(size_t)b*L + i];
    __syncthreads();
    for (int kt = 0; kt < KT; kt++) {
        float bv = -FLT_MAX; int bi = 0x7fffffff;
        for (int i = tid; i < L; i += 256) {
            float v = vals[i];
            if (v > bv || (v == bv && i < bi)) { bv = v; bi = i; }
        }
        #pragma unroll
        for (int o = 16; o > 0; o >>= 1) {
            float ov = __shfl_down_sync(0xffffffffu, bv, o);
            int   oi = __shfl_down_sync(0xffffffffu, bi, o);
            if (ov > bv || (ov == bv && oi < bi)) { bv = ov; bi = oi; }
        }
        if (lane == 0) { wv[wid] = bv; wi[wid] = bi; }
        __syncthreads();
        if (wid == 0) {
            float v2 = (lane < 8) ? wv[lane] : -FLT_MAX;
            int   i2 = (lane < 8) ? wi[lane] : 0x7fffffff;
            #pragma unroll
            for (int o = 4; o > 0; o >>= 1) {
                float ov = __shfl_down_sync(0xffffffffu, v2, o);
                int   oi = __shfl_down_sync(0xffffffffu, i2, o);
                if (ov > v2 || (ov == v2 && oi < i2)) { v2 = ov; i2 = oi; }
            }
            if (lane == 0) { tv[kt] = v2; tix[kt] = i2; vals[i2] = -FLT_MAX; }
        }
        __syncthreads();
    }
    if (tid == 0) {
        float mx = tv[0], s = 0.f;
        float e[32];
        for (int i = 0; i < KT; i++) { e[i] = expf(tv[i] - mx); s += e[i]; }
        float inv = 1.0f / s;
        for (int i = 0; i < KT; i++) {
            wgt[b*32 + i] = e[i] * inv;
            delay[b*32 + i] = tix[i];
        }
    }
}

// ---------------- weighted circular gather (split out) ----------------
__global__ void k_agg(const float* __restrict__ V, int vld, const int* __restrict__ delay,
                      const float* __restrict__ wgt, bf* __restrict__ OH,
                      bf* __restrict__ OL, int L, int S, int KT, long long vbs) {
    int t = blockIdx.x, b = blockIdx.y, d = threadIdx.x;
    __shared__ int sd[32];
    __shared__ float sw[32];
    if (d < KT) { sd[d] = delay[b*32 + d]; sw[d] = wgt[b*32 + d]; }
    __syncthreads();
    float acc = 0.f;
    for (int i = 0; i < KT; i++) {
        int r = t + sd[i]; if (r >= L) r -= L;
        if (r < S) acc += sw[i] * V[(size_t)b*vbs + (size_t)r*vld + d];
    }
    size_t o = ((size_t)b*L + t)*DM_ + d;
    bf h = __float2bfloat16(acc);
    OH[o] = h; OL[o] = __float2bfloat16(acc - __bfloat162float(h));
}

// ---------------- series_decomp on single residual-summed array ----------
__global__ void k_add_decomp2(const float* __restrict__ R,
                              float* __restrict__ S, float* __restrict__ T,
                              bf* __restrict__ SH, bf* __restrict__ SL,
                              int L, int tmode) {
    int b = blockIdx.y, ch = blockIdx.x, d = threadIdx.x;
    int CH = (L + 7) / 8;
    int t0 = ch * CH, t1 = min(t0 + CH, L);
    if (t0 >= L) return;
    const size_t base = (size_t)b * L * DM_ + d;
    float w = 0.f;
    for (int j = -12; j <= 12; j++) {
        int tt = t0 + j; tt = tt < 0 ? 0 : (tt >= L ? L-1 : tt);
        w += R[base + (size_t)tt * DM_];
    }
    for (int t = t0; t < t1; t++) {
        size_t idx = base + (size_t)t * DM_;
        float cur = R[idx];
        float m = w * (1.0f/25.0f);
        float sv = cur - m;
        S[idx] = sv;
        bf h = __float2bfloat16(sv);
        SH[idx] = h; SL[idx] = __float2bfloat16(sv - __bfloat162float(h));
        if (tmode == 1) T[idx] = m;
        else if (tmode == 2) T[idx] += m;
        int ta = t + 13; ta = ta >= L ? L-1 : ta;
        int tr = t - 12; tr = tr < 0 ? 0 : tr;
        w += R[base + (size_t)ta * DM_] - R[base + (size_t)tr * DM_];
    }
}

// ---------------- layernorm ----------------
__global__ void k_ln(const float* __restrict__ X, const float* __restrict__ g,
                     const float* __restrict__ be, float* __restrict__ Y) {
    int row = blockIdx.x, tid = threadIdx.x;
    __shared__ float buf[DM_];
    __shared__ float red[256];
    __shared__ float smu, sinv;
    const float* xr = X + (size_t)row * DM_;
    float s = 0.f;
    for (int i = tid; i < DM_; i += 256) { float v = xr[i]; buf[i] = v; s += v; }
    red[tid] = s; __syncthreads();
    for (int st = 128; st > 0; st >>= 1) { if (tid < st) red[tid] += red[tid+st]; __syncthreads(); }
    if (tid == 0) smu = red[0] * (1.0f/DM_);
    __syncthreads();
    float mu = smu, s2 = 0.f;
    for (int i = tid; i < DM_; i += 256) { float dv = buf[i] - mu; s2 += dv*dv; }
    red[tid] = s2; __syncthreads();
    for (int st = 128; st > 0; st >>= 1) { if (tid < st) red[tid] += red[tid+st]; __syncthreads(); }
    if (tid == 0) sinv = rsqrtf(red[0] * (1.0f/DM_) + 1e-5f);
    __syncthreads();
    float inv = sinv;
    for (int i = tid; i < DM_; i += 256)
        Y[(size_t)row*DM_ + i] = (buf[i] - mu) * inv * g[i] + be[i];
}

__global__ void k_submean2(float* __restrict__ Y, bf* __restrict__ H, bf* __restrict__ L,
                           int Llen) {
    int b = blockIdx.x >> 3, c = blockIdx.x & 7;
    int dl = threadIdx.x & 63, tp = threadIdx.x >> 6;
    int d = c*64 + dl;
    size_t base = (size_t)b*Llen*DM_ + d;
    float s = 0.f;
    for (int t = tp; t < Llen; t += 4) s += Y[base + (size_t)t*DM_];
    __shared__ float red[4][64];
    red[tp][dl] = s; __syncthreads();
    if (tp == 0) red[0][dl] = (red[0][dl]+red[1][dl]+red[2][dl]+red[3][dl]) / (float)Llen;
    __syncthreads();
    float m = red[0][dl];
    for (int t = tp; t < Llen; t += 4) {
        size_t idx = base + (size_t)t*DM_;
        float v = Y[idx] - m;
        Y[idx] = v;
        if (H) {
            bf h = __float2bfloat16(v);
            H[idx] = h; L[idx] = __float2bfloat16(v - __bfloat162float(h));
        }
    }
}

// ---------------- final assembly ----------------
__global__ void k_final(const float* __restrict__ XLN, const float* __restrict__ TS,
                        const float* __restrict__ meanb, const float* __restrict__ Wt,
                        const float* __restrict__ Wp, const float* __restrict__ bp,
                        float* __restrict__ out) {
    int p = blockIdx.x, b = blockIdx.y, tid = threadIdx.x;
    int t = LBL_ + p;
    int r0 = (t - 1 + LD_) % LD_;
    int r2 = (t + 1) % LD_;
    float acc[NC_];
    #pragma unroll
    for (int c = 0; c < NC_; c++) acc[c] = 0.f;
    for (int d = tid; d < DM_; d += 256) {
        float xv  = XLN[((size_t)b*LD_ + t )*DM_ + d];
        float tv0 = TS [((size_t)b*LD_ + r0)*DM_ + d];
        float tv1 = TS [((size_t)b*LD_ + t )*DM_ + d];
        float tv2 = TS [((size_t)b*LD_ + r2)*DM_ + d];
        #pragma unroll
        for (int c = 0; c < NC_; c++) {
            acc[c] += xv  * Wp[(size_t)d*NC_ + c]
                    + tv0 * Wt[((size_t)0*DM_ + d)*NC_ + c]
                    + tv1 * Wt[((size_t)1*DM_ + d)*NC_ + c]
                    + tv2 * Wt[((size_t)2*DM_ + d)*NC_ + c];
        }
    }
    __shared__ float red[256];
    for (int c = 0; c < NC_; c++) {
        red[tid] = acc[c]; __syncthreads();
        for (int st = 128; st > 0; st >>= 1) { if (tid < st) red[tid] += red[tid+st]; __syncthreads(); }
        if (tid == 0)
            out[((size_t)b*PRED_ + p)*NC_ + c] = red[0] + meanb[b*NC_ + c] + bp[c];
        __syncthreads();
    }
}

// ================= host orchestration =================
static bf *ABH, *ABL, *QBH, *QBL, *KBH, *KBL, *HBH, *HBL, *WBH, *WBL;

extern "C" void kernel_launch(void* const* d_in, const int* in_sizes, int n_in,
                              void* d_out, int out_size) {
    const float* x_enc      = (const float*)d_in[0];
    const float* x_mark_enc = (const float*)d_in[1];
    const float* x_mark_dec = (const float*)d_in[3];
    const float* W_enc_emb  = (const float*)d_in[4];
    const float* W_mark_enc = (const float*)d_in[5];
    const float* W_dec_emb  = (const float*)d_in[6];
    const float* W_mark_dec = (const float*)d_in[7];
    const float* eW_attn    = (const float*)d_in[8];
    const float* eb_attn    = (const float*)d_in[9];
    const float* eW1        = (const float*)d_in[10];
    const float* eW2        = (const float*)d_in[11];
    const float* eg         = (const float*)d_in[12];
    const float* ebeta      = (const float*)d_in[13];
    const float* sW         = (const float*)d_in[14];
    const float* sb         = (const float*)d_in[15];
    const float* cW         = (const float*)d_in[16];
    const float* cb         = (const float*)d_in[17];
    const float* dW1        = (const float*)d_in[18];
    const float* dW2        = (const float*)d_in[19];
    const float* W_trend    = (const float*)d_in[20];
    const float* dg         = (const float*)d_in[21];
    const float* dbeta      = (const float*)d_in[22];
    const float* Wproj      = (const float*)d_in[23];
    const float* bproj      = (const float*)d_in[24];
    float* out = (float*)d_out;

    cudaFuncSetAttribute(k_mma, cudaFuncAttributeMaxDynamicSharedMemorySize, SMEM_SZ);

    float* ws = nullptr;
    cudaGetSymbolAddress((void**)&ws, g_ws);
    int* dly = nullptr;
    cudaGetSymbolAddress((void**)&dly, g_delay);
    cudaGetSymbolAddress((void**)&ABH, g_abh);
    cudaGetSymbolAddress((void**)&ABL, g_abl);
    cudaGetSymbolAddress((void**)&QBH, g_qbh);
    cudaGetSymbolAddress((void**)&QBL, g_qbl);
    cudaGetSymbolAddress((void**)&KBH, g_kbh);
    cudaGetSymbolAddress((void**)&KBL, g_kbl);
    cudaGetSymbolAddress((void**)&HBH, g_hbh);
    cudaGetSymbolAddress((void**)&HBL, g_hbl);
    cudaGetSymbolAddress((void**)&WBH, g_wbh);
    cudaGetSymbolAddress((void**)&WBL, g_wbl);

    float* XE   = ws + O_XE;
    float* XA   = ws + O_XA;
    float* XD   = ws + O_XD;
    float* Qb   = ws + O_Q;
    float* Vb   = ws + O_V;
    float* Tb   = ws + O_T;
    float* Gb   = ws + O_G;
    float* CORR = ws + O_CORR;
    float* ENC  = ws + O_ENC;
    float* TS   = ws + O_TS;
    float* SEA  = ws + O_SEA;
    float* MEANB= ws + O_MEAN;
    float* WGT  = ws + O_WGT;

    // ---- fused weight transpose+split ----
    k_cvtT_all<<<10240, dim3(32,8)>>>(eW_attn, eW1, eW2, sW, cW, dW1, dW2, WBH, WBL);

    // ---- prep ----
    k_sea<<<(B_*LE_*NC_ + 255)/256, 256>>>(x_enc, SEA);
    k_meanc<<<B_, 256>>>(x_enc, MEANB);
    k_embed_enc2<<<dim3(LE_/32, B_, 2), 256>>>(x_enc, x_mark_enc, W_enc_emb, W_mark_enc, XE, ABH, ABL);

    // ---- encoder: 2 layers ----
    float* x = XE;
    for (int l = 0; l < 2; l++) {
        const float* bb = eb_attn + (size_t)l*4*DM_;
        size_t wa = OW_EATT + (size_t)l*4*DM_*DM_;
        k_mma<<<dim3(12,128,1), 256, SMEM_SZ>>>(ABH, ABL, DM_, WBH+wa, WBL+wa, DM_,
            DM_, B_*LE_, 1536, 0, 0, 0,
            2, Vb, DM_, QBH, QBL, 0, KBH, KBL, LE_, LE_, 4, 4, nullptr, bb, 0);
        k_mma<<<dim3(4,4,B_), 256, SMEM_SZ>>>(QBH, QBL, DM_, KBH, KBL, DM_,
            DM_, LE_, LE_, (long long)LE_*DM_, (long long)LE_*DM_, (long long)LE_*LE_,
            0, Gb, LE_, nullptr, nullptr, 0, nullptr, nullptr, LE_, LE_, 0, 0, nullptr, nullptr, 0);
        k_zero<<<(B_*LE_ + 255)/256, 256>>>(CORR, B_*LE_);
        k_corr2<<<dim3(LE_/16, B_), 256>>>(Gb, CORR, LE_, LE_*LE_);
        k_topk<<<B_, 256>>>(CORR, LE_, KT_E, dly, WGT);
        k_agg<<<dim3(LE_, B_), DM_>>>(Vb, DM_, dly, WGT, ABH, ABL,
                                      LE_, LE_, KT_E, (long long)LE_*DM_);
        k_mma<<<dim3(4,128,1), 256, SMEM_SZ>>>(ABH, ABL, DM_,
            WBH+wa+3*(size_t)DM_*DM_, WBL+wa+3*(size_t)DM_*DM_, DM_,
            DM_, B_*LE_, DM_, 0, 0, 0,
            0, Tb, DM_, nullptr, nullptr, 0, nullptr, nullptr, LE_, LE_, 0, 0, x, bb+3*DM_, 0);
        float* nx = (x == XE) ? XA : XE;
        k_add_decomp2<<<dim3(8, B_), DM_>>>(Tb, nx, nullptr, ABH, ABL, LE_, 0);
        x = nx;
        k_mma<<<dim3(16,128,1), 256, SMEM_SZ>>>(ABH, ABL, DM_,
            WBH+OW_EW1+(size_t)l*DM_*DFF_, WBL+OW_EW1+(size_t)l*DM_*DFF_, DM_,
            DM_, B_*LE_, DFF_, 0, 0, 0,
            1, nullptr, 0, HBH, HBL, DFF_, nullptr, nullptr, LE_, LE_, 0, 0, nullptr, nullptr, 1);
        k_mma<<<dim3(4,128,1), 256, SMEM_SZ>>>(HBH, HBL, DFF_,
            WBH+OW_EW2+(size_t)l*DFF_*DM_, WBL+OW_EW2+(size_t)l*DFF_*DM_, DFF_,
            DFF_, B_*LE_, DM_, 0, 0, 0,
            0, Tb, DM_, nullptr, nullptr, 0, nullptr, nullptr, LE_, LE_, 0, 0, x, nullptr, 0);
        nx = (x == XE) ? XA : XE;
        k_add_decomp2<<<dim3(8, B_), DM_>>>(Tb, nx, nullptr, ABH, ABL, LE_, 0);
        x = nx;
    }
    k_ln<<<B_*LE_, 256>>>(x, eg, ebeta, ENC);
    k_submean2<<<B_*8, 256>>>(ENC, HBH, HBL, LE_);   // ENC split cached in HBH/HBL

    // ---- decoder ----
    k_embed_dec2<<<dim3((LD_+31)/32, B_, 2), 256>>>(SEA, x_mark_enc, x_mark_dec,
                                                    W_dec_emb, W_mark_dec, XD, ABH, ABL);
    float* xd = XD;

    // zero pad rows [592,640) of QB/KB (dirtied by encoder usage)
    {
        int n = B_*(LP_-LD_)*DM_;
        k_padzero<<<(n+255)/256, 256>>>(QBH, QBL, LD_);
        k_padzero<<<(n+255)/256, 256>>>(KBH, KBL, LD_);
    }

    // self attention
    k_mma<<<dim3(12,148,1), 256, SMEM_SZ>>>(ABH, ABL, DM_, WBH+OW_SW, WBL+OW_SW, DM_,
        DM_, B_*LD_, 1536, 0, 0, 0,
        2, Vb, DM_, QBH, QBL, 0, KBH, KBL, LD_, LP_, 4, 4, nullptr, sb, 0);
    k_mma<<<dim3(5,5,B_), 256, SMEM_SZ>>>(QBH, QBL, DM_, KBH, KBL, DM_,
        DM_, LD_, LD_, (long long)LP_*DM_, (long long)LP_*DM_, (long long)LD_*LD_,
        0, Gb, LD_, nullptr, nullptr, 0, nullptr, nullptr, LD_, LD_, 0, 0, nullptr, nullptr, 0);
    k_zero<<<(B_*LD_ + 255)/256, 256>>>(CORR, B_*LD_);
    k_corr2<<<dim3((LD_+15)/16, B_), 256>>>(Gb, CORR, LD_, LD_*LD_);
    k_topk<<<B_, 256>>>(CORR, LD_, KT_D, dly, WGT);
    k_agg<<<dim3(LD_, B_), DM_>>>(Vb, DM_, dly, WGT, ABH, ABL,
                                  LD_, LD_, KT_D, (long long)LD_*DM_);
    k_mma<<<dim3(4,148,1), 256, SMEM_SZ>>>(ABH, ABL, DM_,
        WBH+OW_SW+3*(size_t)DM_*DM_, WBL+OW_SW+3*(size_t)DM_*DM_, DM_,
        DM_, B_*LD_, DM_, 0, 0, 0,
        0, Tb, DM_, nullptr, nullptr, 0, nullptr, nullptr, LD_, LD_, 0, 0, xd, sb+3*DM_, 0);
    k_add_decomp2<<<dim3(8, B_), DM_>>>(Tb, XA, TS, ABH, ABL, LD_, 1);
    xd = XA;

    // cross attention: Q from x (padded split), K/V merged from ENC split
    k_mma<<<dim3(4,148,1), 256, SMEM_SZ>>>(ABH, ABL, DM_, WBH+OW_CW, WBL+OW_CW, DM_,
        DM_, B_*LD_, DM_, 0, 0, 0,
        1, nullptr, 0, QBH, QBL, DM_, nullptr, nullptr, LD_, LP_, 0, 0, nullptr, cb, 0);
    {
        int n = B_*(LP_-LE_)*DM_;
        k_padzero<<<(n+255)/256, 256>>>(KBH, KBL, LE_);
    }
    k_mma<<<dim3(8,128,1), 256, SMEM_SZ>>>(HBH, HBL, DM_,
        WBH+OW_CW+(size_t)DM_*DM_, WBL+OW_CW+(size_t)DM_*DM_, DM_,
        DM_, B_*LE_, 1024, 0, 0, 0,
        3, Vb, DM_, nullptr, nullptr, 0, KBH, KBL, LE_, LP_, 0, 4, nullptr, cb+DM_, 0);
    k_mma<<<dim3(5,5,B_), 256, SMEM_SZ>>>(QBH, QBL, DM_, KBH, KBL, DM_,
        DM_, LD_, LD_, (long long)LP_*DM_, (long long)LP_*DM_, (long long)LD_*LD_,
        0, Gb, LD_, nullptr, nullptr, 0, nullptr, nullptr, LD_, LD_, 0, 0, nullptr, nullptr, 0);
    k_zero<<<(B_*LD_ + 255)/256, 256>>>(CORR, B_*LD_);
    k_corr2<<<dim3((LD_+15)/16, B_), 256>>>(Gb, CORR, LD_, LD_*LD_);
    k_topk<<<B_, 256>>>(CORR, LD_, KT_D, dly, WGT);
    k_agg<<<dim3(LD_, B_), DM_>>>(Vb, DM_, dly, WGT, ABH, ABL,
                                  LD_, LE_, KT_D, (long long)LE_*DM_);
    k_mma<<<dim3(4,148,1), 256, SMEM_SZ>>>(ABH, ABL, DM_,
        WBH+OW_CW+3*(size_t)DM_*DM_, WBL+OW_CW+3*(size_t)DM_*DM_, DM_,
        DM_, B_*LD_, DM_, 0, 0, 0,
        0, Tb, DM_, nullptr, nullptr, 0, nullptr, nullptr, LD_, LD_, 0, 0, xd, cb+3*DM_, 0);
    k_add_decomp2<<<dim3(8, B_), DM_>>>(Tb, XD, TS, ABH, ABL, LD_, 2);
    xd = XD;

    // FFN
    k_mma<<<dim3(16,148,1), 256, SMEM_SZ>>>(ABH, ABL, DM_,
        WBH+OW_DW1, WBL+OW_DW1, DM_,
        DM_, B_*LD_, DFF_, 0, 0, 0,
        1, nullptr, 0, HBH, HBL, DFF_, nullptr, nullptr, LD_, LD_, 0, 0, nullptr, nullptr, 1);
    k_mma<<<dim3(4,148,1), 256, SMEM_SZ>>>(HBH, HBL, DFF_,
        WBH+OW_DW2, WBL+OW_DW2, DFF_,
        DFF_, B_*LD_, DM_, 0, 0, 0,
        0, Tb, DM_, nullptr, nullptr, 0, nullptr, nullptr, LD_, LD_, 0, 0, xd, nullptr, 0);
    k_add_decomp2<<<dim3(8, B_), DM_>>>(Tb, XA, TS, ABH, ABL, LD_, 2);
    xd = XA;

    // final layernorm + output assembly
    k_ln<<<B_*LD_, 256>>>(xd, dg, dbeta, Qb);
    k_submean2<<<B_*8, 256>>>(Qb, nullptr, nullptr, LD_);
    k_final<<<dim3(PRED_, B_), 256>>>(Qb, TS, MEANB, W_trend, Wproj, bproj, out);
}

// round 13
// speedup vs baseline: 1.0588x; 1.0325x over previous
#include <cuda_runtime.h>
#include <cuda_bf16.h>
#include <math.h>
#include <float.h>
#include <stdint.h>

typedef __nv_bfloat16 bf;

#define B_    32
#define LE_   512
#define LD_   592
#define LP_   640
#define DM_   512
#define DFF_  2048
#define NC_   7
#define NM_   4
#define LBL_  256
#define PRED_ 336
#define KT_E  18
#define KT_D  19

#define SZ_XE  ((size_t)B_*LE_*DM_)
#define SZ_XD  ((size_t)B_*LD_*DM_)
#define SZ_G   ((size_t)B_*LD_*LD_)

#define O_XE   ((size_t)0)
#define O_XA   (O_XE + SZ_XE)
#define O_XD   (O_XA + SZ_XD)
#define O_Q    (O_XD + SZ_XD)
#define O_V    (O_Q  + SZ_XD)
#define O_T    (O_V  + SZ_XD)
#define O_G    (O_T  + SZ_XD)
#define O_CORR (O_G  + SZ_G)
#define O_ENC  (O_CORR + (size_t)B_*LD_)
#define O_TS   (O_ENC + SZ_XE)
#define O_SEA  (O_TS + SZ_XD)
#define O_MEAN (O_SEA + (size_t)B_*LE_*NC_)
#define O_WGT  (O_MEAN + (size_t)B_*NC_)
#define WS_TOTAL (O_WGT + (size_t)B_*32)

__device__ __align__(256) float g_ws[WS_TOTAL];
__device__ int g_delay[B_*32];
__device__ int g_delay2[B_*32];

#define OD_T   ((size_t)0)
#define OD_G   (OD_T + SZ_XD)
#define OD_CORR (OD_G + SZ_G)
#define OD_WGT (OD_CORR + (size_t)B_*LD_)
#define DWS_TOTAL (OD_WGT + (size_t)B_*32)
__device__ __align__(256) float g_dws[DWS_TOTAL];

#define SZ_AB  ((size_t)B_*LP_*DM_)
#define SZ_QB  ((size_t)B_*LP_*DM_)
#define SZ_KB  ((size_t)B_*LP_*DM_)
#define SZ_HB  ((size_t)B_*LD_*DFF_)
#define OW_EATT ((size_t)0)
#define OW_EW1  ((size_t)2097152)
#define OW_EW2  ((size_t)4194304)
#define OW_SW   ((size_t)6291456)
#define OW_CW   ((size_t)7340032)
#define OW_DW1  ((size_t)8388608)
#define OW_DW2  ((size_t)9437184)
#define SZ_WB   ((size_t)10485760)

__device__ __align__(256) bf g_abh[SZ_AB];
__device__ __align__(256) bf g_abl[SZ_AB];
__device__ __align__(256) bf g_qbh[SZ_QB];
__device__ __align__(256) bf g_qbl[SZ_QB];
__device__ __align__(256) bf g_kbh[SZ_KB];
__device__ __align__(256) bf g_kbl[SZ_KB];
__device__ __align__(256) bf g_hbh[SZ_HB];
__device__ __align__(256) bf g_hbl[SZ_HB];
__device__ __align__(256) bf g_wbh[SZ_WB];
__device__ __align__(256) bf g_wbl[SZ_WB];
__device__ __align__(256) bf g_dbh[SZ_AB];
__device__ __align__(256) bf g_dbl[SZ_AB];
__device__ __align__(256) bf g_dqh[SZ_QB];
__device__ __align__(256) bf g_dql[SZ_QB];
__device__ __align__(256) bf g_dkh[SZ_KB];
__device__ __align__(256) bf g_dkl[SZ_KB];

__device__ __forceinline__ float gelu_exact(float v) {
    return 0.5f * v * (1.0f + erff(v * 0.70710678118654752440f));
}
__device__ __forceinline__ uint32_t s2u(const void* p){
    uint32_t a;
    asm("{ .reg .u64 t; cvta.to.shared.u64 t, %1; cvt.u32.u64 %0, t; }":"=r"(a):"l"(p));
    return a;
}
#define SWZ(o) ((o) ^ (((o)>>3)&0x70))

#define LDSM4(r, ad) \
    asm volatile("ldmatrix.sync.aligned.m8n8.x4.shared.b16 {%0,%1,%2,%3}, [%4];" \
        : "=r"((r)[0]), "=r"((r)[1]), "=r"((r)[2]), "=r"((r)[3]) : "r"(ad))

#define MMA16816(d, a, b0, b1) \
    asm volatile("mma.sync.aligned.m16n8k16.row.col.f32.bf16.bf16.f32 " \
        "{%0,%1,%2,%3}, {%4,%5,%6,%7}, {%8,%9}, {%0,%1,%2,%3};" \
        : "+f"((d)[0]), "+f"((d)[1]), "+f"((d)[2]), "+f"((d)[3]) \
        : "r"((a)[0]), "r"((a)[1]), "r"((a)[2]), "r"((a)[3]), "r"(b0), "r"(b1))

__device__ __forceinline__ void split_store(bf* H, bf* L, size_t o, float v0, float v1){
    bf h0 = __float2bfloat16(v0), h1 = __float2bfloat16(v1);
    bf l0 = __float2bfloat16(v0 - __bfloat162float(h0));
    bf l1 = __float2bfloat16(v1 - __bfloat162float(h1));
    *(__nv_bfloat162*)(H + o) = __nv_bfloat162(h0, h1);
    *(__nv_bfloat162*)(L + o) = __nv_bfloat162(l0, l1);
}

__global__ void k_cvtT_all(const float* __restrict__ eatt, const float* __restrict__ e1,
                           const float* __restrict__ e2, const float* __restrict__ sw,
                           const float* __restrict__ cw, const float* __restrict__ d1,
                           const float* __restrict__ d2,
                           bf* __restrict__ WH, bf* __restrict__ WL){
    __shared__ float t[32][33];
    int blk = blockIdx.x;
    const float* src; size_t dstoff; int K, N, mi, tt;
    if (blk < 2048)       { src=eatt; dstoff=OW_EATT; K=512; N=512;  mi=blk/256;        tt=blk%256; }
    else if (blk < 4096)  { src=e1;   dstoff=OW_EW1;  K=512; N=2048; mi=(blk-2048)/1024; tt=(blk-2048)%1024; }
    else if (blk < 6144)  { src=e2;   dstoff=OW_EW2;  K=2048;N=512;  mi=(blk-4096)/1024; tt=(blk-4096)%1024; }
    else if (blk < 7168)  { src=sw;   dstoff=OW_SW;   K=512; N=512;  mi=(blk-6144)/256;  tt=(blk-6144)%256; }
    else if (blk < 8192)  { src=cw;   dstoff=OW_CW;   K=512; N=512;  mi=(blk-7168)/256;  tt=(blk-7168)%256; }
    else if (blk < 9216)  { src=d1;   dstoff=OW_DW1;  K=512; N=2048; mi=0;               tt=blk-8192; }
    else                  { src=d2;   dstoff=OW_DW2;  K=2048;N=512;  mi=0;               tt=blk-9216; }
    int tn = N/32;
    int n0 = (tt % tn)*32, k0 = (tt / tn)*32;
    const float* W = src + (size_t)mi*K*N;
    bf* TH = WH + dstoff + (size_t)mi*K*N;
    bf* TL = WL + dstoff + (size_t)mi*K*N;
    int tx = threadIdx.x, ty = threadIdx.y;
    #pragma unroll
    for (int i = 0; i < 32; i += 8)
        t[ty+i][tx] = W[(size_t)(k0+ty+i)*N + n0 + tx];
    __syncthreads();
    #pragma unroll
    for (int i = 0; i < 32; i += 8) {
        float x = t[tx][ty+i];
        bf h = __float2bfloat16(x);
        size_t o = (size_t)(n0+ty+i)*K + k0 + tx;
        TH[o] = h; TL[o] = __float2bfloat16(x - __bfloat162float(h));
    }
}

#define SMEM_SZ 131072

__device__ __forceinline__ void ldchunk(uint32_t st,
    const bf* __restrict__ A_h, const bf* __restrict__ A_l, int lda,
    const bf* __restrict__ B_h, const bf* __restrict__ B_l, int ldb,
    int k0, int tid)
{
    const bf* srcs[4] = {A_h, A_l, B_h, B_l};
    const int lds[4] = {lda, lda, ldb, ldb};
    #pragma unroll
    for (int t = 0; t < 4; t++) {
        #pragma unroll
        for (int i = 0; i < 4; i++) {
            int idx = i*256 + tid;
            int row = idx >> 3, c16 = idx & 7;
            uint32_t dst = st + t*16384 + SWZ(row*128 + c16*16);
            const bf* src = srcs[t] + (size_t)row*lds[t] + k0 + c16*8;
            asm volatile("cp.async.cg.shared.global [%0], [%1], 16;\n"::"r"(dst),"l"(src));
        }
    }
    asm volatile("cp.async.commit_group;\n":::"memory");
}

__global__ void __launch_bounds__(256,1) k_mma(
    const bf* __restrict__ Ah, const bf* __restrict__ Al, int lda,
    const bf* __restrict__ Bh, const bf* __restrict__ Bl, int ldb,
    int K, int rowsV, int colsV,
    long long aB, long long bB, long long cB,
    int mode, float* __restrict__ C, int ldc,
    bf* __restrict__ H0, bf* __restrict__ L0, int ldh0,
    bf* __restrict__ H1, bf* __restrict__ L1,
    int Lv, int Lp, int nq, int nk,
    const float* __restrict__ RES, const float* __restrict__ bias, int act)
{
    extern __shared__ char smem[];
    uint32_t sb0 = s2u(smem);
    const int tid = threadIdx.x, lane = tid & 31, wid = tid >> 5;
    const int bn = blockIdx.x, bm = blockIdx.y, bz = blockIdx.z;
    const bf* Ah2 = Ah + (size_t)bz*aB + (size_t)bm*128*lda;
    const bf* Al2 = Al + (size_t)bz*aB + (size_t)bm*128*lda;
    const bf* Bh2 = Bh + (size_t)bz*bB + (size_t)bn*128*ldb;
    const bf* Bl2 = Bl + (size_t)bz*bB + (size_t)bn*128*ldb;
    if (C) C += (size_t)bz*cB;

    float acc[4][4][4];
    #pragma unroll
    for (int i = 0; i < 4; i++)
        #pragma unroll
        for (int j = 0; j < 4; j++)
            #pragma unroll
            for (int q = 0; q < 4; q++) acc[i][j][q] = 0.f;

    const int KC = K >> 6;
    const int m0 = (wid & 1) << 6, n0 = (wid >> 1) << 5;

    ldchunk(sb0, Ah2, Al2, lda, Bh2, Bl2, ldb, 0, tid);

    for (int c = 0; c < KC; c++) {
        uint32_t st = sb0 + (uint32_t)(c & 1) * 65536u;
        if (c+1 < KC) {
            ldchunk(sb0 + (uint32_t)((c+1) & 1) * 65536u,
                    Ah2, Al2, lda, Bh2, Bl2, ldb, (c+1)*64, tid);
            asm volatile("cp.async.wait_group 1;\n":::"memory");
        } else {
            asm volatile("cp.async.wait_group 0;\n":::"memory");
        }
        __syncthreads();

        #pragma unroll
        for (int kk = 0; kk < 4; kk++) {
            uint32_t afh[4][4], afl[4][4], bfh[2][4], bfl[2][4];
            #pragma unroll
            for (int mt = 0; mt < 4; mt++) {
                int m = m0 + mt*16 + (lane & 15);
                int kb = kk*32 + ((lane >> 4) << 4);
                uint32_t off = SWZ(m*128 + kb);
                LDSM4(afh[mt], st + off);
                LDSM4(afl[mt], st + 16384u + off);
            }
            #pragma unroll
            for (int nt2 = 0; nt2 < 2; nt2++) {
                int g = lane >> 3;
                int n = n0 + nt2*16 + ((g >> 1) << 3) + (lane & 7);
                int kb = kk*32 + ((g & 1) << 4);
                uint32_t off = SWZ(n*128 + kb);
                LDSM4(bfh[nt2], st + 32768u + off);
                LDSM4(bfl[nt2], st + 49152u + off);
            }
            #pragma unroll
            for (int mt = 0; mt < 4; mt++)
                #pragma unroll
                for (int nt = 0; nt < 4; nt++)
                    MMA16816(acc[mt][nt], afh[mt],
                             bfh[nt>>1][(nt&1)*2], bfh[nt>>1][(nt&1)*2+1]);
            #pragma unroll
            for (int mt = 0; mt < 4; mt++)
                #pragma unroll
                for (int nt = 0; nt < 4; nt++)
                    MMA16816(acc[mt][nt], afh[mt],
                             bfl[nt>>1][(nt&1)*2], bfl[nt>>1][(nt&1)*2+1]);
            #pragma unroll
            for (int mt = 0; mt < 4; mt++)
                #pragma unroll
                for (int nt = 0; nt < 4; nt++)
                    MMA16816(acc[mt][nt], afl[mt],
                             bfh[nt>>1][(nt&1)*2], bfh[nt>>1][(nt&1)*2+1]);
        }
        __syncthreads();
    }

    const int gid = lane >> 2, tig = lane & 3;
    const int nq128 = nq*128, nqk128 = (nq+nk)*128;
    #pragma unroll
    for (int mt = 0; mt < 4; mt++) {
        #pragma unroll
        for (int h = 0; h < 2; h++) {
            int row = bm*128 + m0 + mt*16 + gid + h*8;
            if (row >= rowsV) continue;
            int bq = row / Lv, rr = row - bq*Lv;
            size_t prow = (size_t)bq*Lp + rr;
            #pragma unroll
            for (int nt = 0; nt < 4; nt++) {
                int col = bn*128 + n0 + nt*8 + tig*2;
                if (col >= colsV) continue;
                float v0 = acc[mt][nt][h*2+0];
                float v1 = acc[mt][nt][h*2+1];
                if (bias) { v0 += bias[col]; v1 += bias[col+1]; }
                if (act)  { v0 = gelu_exact(v0); v1 = gelu_exact(v1); }
                if (mode == 0) {
                    size_t o = (size_t)row*ldc + col;
                    if (RES) { float2 r2 = *(const float2*)(RES + o); v0 += r2.x; v1 += r2.y; }
                    *(float2*)(C + o) = make_float2(v0, v1);
                } else if (mode == 1) {
                    split_store(H0, L0, prow*ldh0 + col, v0, v1);
                } else {
                    if (col < nq128)
                        split_store(H0, L0, prow*DM_ + col, v0, v1);
                    else if (col < nqk128)
                        split_store(H1, L1, prow*DM_ + (col - nq128), v0, v1);
                    else
                        *(float2*)(C + (size_t)row*ldc + (col - nqk128)) = make_float2(v0, v1);
                }
            }
        }
    }
}

__global__ void k_sea(const float* __restrict__ xe, float* __restrict__ sea) {
    int i = blockIdx.x * blockDim.x + threadIdx.x;
    if (i >= B_*LE_*NC_) return;
    int c = i % NC_;
    int t = (i / NC_) % LE_;
    int b = i / (NC_*LE_);
    float s = 0.f;
    #pragma unroll
    for (int j = -12; j <= 12; j++) {
        int tt = t + j; tt = tt < 0 ? 0 : (tt >= LE_ ? LE_-1 : tt);
        s += xe[((size_t)b*LE_ + tt)*NC_ + c];
    }
    sea[i] = xe[i] - s * (1.0f/25.0f);
}

__global__ void k_meanc(const float* __restrict__ xe, float* __restrict__ mb) {
    int b = blockIdx.x, tid = threadIdx.x;
    __shared__ float red[7][32];
    if (tid < 224) {
        int c = tid % NC_, slot = tid / NC_;
        float s = 0.f;
        for (int t = slot; t < LE_; t += 32) s += xe[((size_t)b*LE_ + t)*NC_ + c];
        red[c][slot] = s;
    }
    __syncthreads();
    if (tid < NC_) {
        float s = 0.f;
        #pragma unroll
        for (int j = 0; j < 32; j++) s += red[tid][j];
        mb[b*NC_ + tid] = s * (1.0f/LE_);
    }
}

__global__ void k_embed_enc2(const float* __restrict__ xe, const float* __restrict__ mk,
                             const float* __restrict__ Wemb, const float* __restrict__ Wm,
                             float* __restrict__ out, bf* __restrict__ H, bf* __restrict__ Lo) {
    int tc = blockIdx.x, b = blockIdx.y, dh = blockIdx.z;
    int tid = threadIdx.x;
    int d = dh*256 + tid;
    __shared__ float sw[25][256];
    __shared__ float sx[34][NC_];
    __shared__ float sm[32][NM_];
    for (int i = tid; i < 21*256; i += 256) {
        int j = i >> 8, dd = i & 255;
        sw[j][dd] = Wemb[(size_t)j*DM_ + dh*256 + dd];
    }
    for (int i = tid; i < 4*256; i += 256) {
        int m = i >> 8, dd = i & 255;
        sw[21+m][dd] = Wm[(size_t)m*DM_ + dh*256 + dd];
    }
    int t0 = tc*32;
    for (int i = tid; i < 34*NC_; i += 256) {
        int rr = i / NC_, c = i % NC_;
        int r = (t0 - 1 + rr + LE_) % LE_;
        sx[rr][c] = xe[((size_t)b*LE_ + r)*NC_ + c];
    }
    for (int i = tid; i < 32*NM_; i += 256) {
        int rr = i / NM_, m = i % NM_;
        sm[rr][m] = mk[((size_t)b*LE_ + t0 + rr)*NM_ + m];
    }
    __syncthreads();
    for (int tt = 0; tt < 32; tt++) {
        float acc = 0.f;
        #pragma unroll
        for (int j = 0; j < 3; j++)
            #pragma unroll
            for (int c = 0; c < NC_; c++)
                acc += sx[tt + j][c] * sw[j*NC_ + c][tid];
        #pragma unroll
        for (int m = 0; m < NM_; m++) acc += sm[tt][m] * sw[21+m][tid];
        size_t o = ((size_t)b*LE_ + t0 + tt)*DM_ + d;
        out[o] = acc;
        bf h = __float2bfloat16(acc);
        H[o] = h; Lo[o] = __float2bfloat16(acc - __bfloat162float(h));
    }
}

__global__ void k_embed_dec2(const float* __restrict__ sea, const float* __restrict__ mk_enc,
                             const float* __restrict__ mk_dec,
                             const float* __restrict__ Wemb, const float* __restrict__ Wm,
                             float* __restrict__ out, bf* __restrict__ H, bf* __restrict__ Lo) {
    int tc = blockIdx.x, b = blockIdx.y, dh = blockIdx.z;
    int tid = threadIdx.x;
    int d = dh*256 + tid;
    __shared__ float sw[25][256];
    __shared__ float sx[34][NC_];
    __shared__ float sm[32][NM_];
    for (int i = tid; i < 21*256; i += 256) {
        int j = i >> 8, dd = i & 255;
        sw[j][dd] = Wemb[(size_t)j*DM_ + dh*256 + dd];
    }
    for (int i = tid; i < 4*256; i += 256) {
        int m = i >> 8, dd = i & 255;
        sw[21+m][dd] = Wm[(size_t)m*DM_ + dh*256 + dd];
    }
    int t0 = tc*32;
    for (int i = tid; i < 34*NC_; i += 256) {
        int rr = i / NC_, c = i % NC_;
        int r = (t0 - 1 + rr + LD_) % LD_;
        sx[rr][c] = (r < LBL_) ? sea[((size_t)b*LE_ + LBL_ + r)*NC_ + c] : 0.f;
    }
    for (int i = tid; i < 32*NM_; i += 256) {
        int rr = i / NM_, m = i % NM_;
        int t = t0 + rr;
        float v = 0.f;
        if (t < LD_) {
            v = (t < LBL_) ? mk_enc[((size_t)b*LE_ + LBL_ + t)*NM_ + m]
                           : mk_dec[((size_t)b*PRED_ + (t - LBL_))*NM_ + m];
        }
        sm[rr][m] = v;
    }
    __syncthreads();
    for (int tt = 0; tt < 32; tt++) {
        int t = t0 + tt;
        if (t >= LD_) break;
        float acc = 0.f;
        #pragma unroll
        for (int j = 0; j < 3; j++)
            #pragma unroll
            for (int c = 0; c < NC_; c++)
                acc += sx[tt + j][c] * sw[j*NC_ + c][tid];
        #pragma unroll
        for (int m = 0; m < NM_; m++) acc += sm[tt][m] * sw[21+m][tid];
        size_t o = ((size_t)b*LD_ + t)*DM_ + d;
        out[o] = acc;
        bf h = __float2bfloat16(acc);
        H[o] = h; Lo[o] = __float2bfloat16(acc - __bfloat162float(h));
    }
}

__global__ void k_padzero(bf* __restrict__ H, bf* __restrict__ L, int Lv){
    int span = LP_ - Lv;
    int n = B_*span*DM_;
    int i = blockIdx.x*256 + threadIdx.x;
    if (i >= n) return;
    int d = i % DM_;
    int rr = (i / DM_) % span;
    int b = i / (DM_*span);
    size_t o = ((size_t)b*LP_ + Lv + rr)*DM_ + d;
    H[o] = __float2bfloat16(0.f);
    L[o] = __float2bfloat16(0.f);
}

__global__ void k_zero(float* __restrict__ p, int n){
    int i = blockIdx.x*256 + threadIdx.x;
    if (i < n) p[i] = 0.f;
}

__global__ void k_corr2(const float* __restrict__ G, float* __restrict__ corr,
                        int L, int gbs) {
    int b = blockIdx.y, tid = threadIdx.x;
    int t0 = blockIdx.x * 16;
    __shared__ float cs[640];
    for (int i = tid; i < L; i += 256) cs[i] = 0.f;
    __syncthreads();
    const float* Gb = G + (size_t)b*gbs;
    int t1 = min(t0 + 16, L);
    for (int t = t0; t < t1; t++) {
        const float* row = Gb + (size_t)t*L;
        for (int j = tid; j < L; j += 256) {
            int tau = t - j; if (tau < 0) tau += L;
            atomicAdd(&cs[tau], row[j]);
        }
    }
    __syncthreads();
    for (int i = tid; i < L; i += 256)
        atomicAdd(&corr[(size_t)b*L + i], cs[i] * (1.0f/DM_));
}

__global__ void k_topk(const float* __restrict__ corr, int L, int KT,
                       int* __restrict__ delay, float* __restrict__ wgt) {
    int b = blockIdx.x, tid = threadIdx.x;
    int lane = tid & 31, wid = tid >> 5;
    __shared__ float vals[640];
    __shared__ float wv[8];
    __shared__ int wi[8];
    __shared__ float tv[32];
    __shared__ int tix[32];
    for (int i = tid; i < L; i += 256) vals[i] = corr[(size_t)b*L + i];
    __syncthreads();
    for (int kt = 0; kt < KT; kt++) {
        float bv = -FLT_MAX; int bi = 0x7fffffff;
        for (int i = tid; i < L; i += 256) {
            float v = vals[i];
            if (v > bv || (v == bv && i < bi)) { bv = v; bi = i; }
        }
        #pragma unroll
        for (int o = 16; o > 0; o >>= 1) {
            float ov = __shfl_down_sync(0xffffffffu, bv, o);
            int   oi = __shfl_down_sync(0xffffffffu, bi, o);
            if (ov > bv || (ov == bv && oi < bi)) { bv = ov; bi = oi; }
        }
        if (lane == 0) { wv[wid] = bv; wi[wid] = bi; }
        __syncthreads();
        if (wid == 0) {
            float v2 = (lane < 8) ? wv[lane] : -FLT_MAX;
            int   i2 = (lane < 8) ? wi[lane] : 0x7fffffff;
            #pragma unroll
            for (int o = 4; o > 0; o >>= 1) {
                float ov = __shfl_down_sync(0xffffffffu, v2, o);
                int   oi = __shfl_down_sync(0xffffffffu, i2, o);
                if (ov > v2 || (ov == v2 && oi < i2)) { v2 = ov; i2 = oi; }
            }
            if (lane == 0) { tv[kt] = v2; tix[kt] = i2; vals[i2] = -FLT_MAX; }
        }
        __syncthreads();
    }
    if (tid == 0) {
        float mx = tv[0], s = 0.f;
        float e[32];
        for (int i = 0; i < KT; i++) { e[i] = expf(tv[i] - mx); s += e[i]; }
        float inv = 1.0f / s;
        for (int i = 0; i < KT; i++) {
            wgt[b*32 + i] = e[i] * inv;
            delay[b*32 + i] = tix[i];
        }
    }
}

__global__ void k_agg(const float* __restrict__ V, int vld, const int* __restrict__ delay,
                      const float* __restrict__ wgt, bf* __restrict__ OH,
                      bf* __restrict__ OL, int L, int S, int KT, long long vbs) {
    int t = blockIdx.x, b = blockIdx.y, d = threadIdx.x;
    __shared__ int sd[32];
    __shared__ float sw[32];
    if (d < KT) { sd[d] = delay[b*32 + d]; sw[d] = wgt[b*32 + d]; }
    __syncthreads();
    float acc = 0.f;
    for (int i = 0; i < KT; i++) {
        int r = t + sd[i]; if (r >= L) r -= L;
        if (r < S) acc += sw[i] * V[(size_t)b*vbs + (size_t)r*vld + d];
    }
    size_t o = ((size_t)b*L + t)*DM_ + d;
    bf h = __float2bfloat16(acc);
    OH[o] = h; OL[o] = __float2bfloat16(acc - __bfloat162float(h));
}

__global__ void k_add_decomp2(const float* __restrict__ R,
                              float* __restrict__ S, float* __restrict__ T,
                              bf* __restrict__ SH, bf* __restrict__ SL,
                              int L, int tmode) {
    int b = blockIdx.y, ch = blockIdx.x, d = threadIdx.x;
    int CH = (L + 7) / 8;
    int t0 = ch * CH, t1 = min(t0 + CH, L);
    if (t0 >= L) return;
    const size_t base = (size_t)b * L * DM_ + d;
    float w = 0.f;
    for (int j = -12; j <= 12; j++) {
        int tt = t0 + j; tt = tt < 0 ? 0 : (tt >= L ? L-1 : tt);
        w += R[base + (size_t)tt * DM_];
    }
    for (int t = t0; t < t1; t++) {
        size_t idx = base + (size_t)t * DM_;
        float cur = R[idx];
        float m = w * (1.0f/25.0f);
        float sv = cur - m;
        S[idx] = sv;
        bf h = __float2bfloat16(sv);
        SH[idx] = h; SL[idx] = __float2bfloat16(sv - __bfloat162float(h));
        if (tmode == 1) T[idx] = m;
        else if (tmode == 2) T[idx] += m;
        int ta = t + 13; ta = ta >= L ? L-1 : ta;
        int tr = t - 12; tr = tr < 0 ? 0 : tr;
        w += R[base + (size_t)ta * DM_] - R[base + (size_t)tr * DM_];
    }
}

__global__ void k_ln(const float* __restrict__ X, const float* __restrict__ g,
                     const float* __restrict__ be, float* __restrict__ Y) {
    int row = blockIdx.x, tid = threadIdx.x;
    __shared__ float buf[DM_];
    __shared__ float red[256];
    __shared__ float smu, sinv;
    const float* xr = X + (size_t)row * DM_;
    float s = 0.f;
    for (int i = tid; i < DM_; i += 256) { float v = xr[i]; buf[i] = v; s += v; }
    red[tid] = s; __syncthreads();
    for (int st = 128; st > 0; st >>= 1) { if (tid < st) red[tid] += red[tid+st]; __syncthreads(); }
    if (tid == 0) smu = red[0] * (1.0f/DM_);
    __syncthreads();
    float mu = smu, s2 = 0.f;
    for (int i = tid; i < DM_; i += 256) { float dv = buf[i] - mu; s2 += dv*dv; }
    red[tid] = s2; __syncthreads();
    for (int st = 128; st > 0; st >>= 1) { if (tid < st) red[tid] += red[tid+st]; __syncthreads(); }
    if (tid == 0) sinv = rsqrtf(red[0] * (1.0f/DM_) + 1e-5f);
    __syncthreads();
    float inv = sinv;
    for (int i = tid; i < DM_; i += 256)
        Y[(size_t)row*DM_ + i] = (buf[i] - mu) * inv * g[i] + be[i];
}

__global__ void k_submean2(float* __restrict__ Y, bf* __restrict__ H, bf* __restrict__ L,
                           int Llen) {
    int b = blockIdx.x >> 3, c = blockIdx.x & 7;
    int dl = threadIdx.x & 63, tp = threadIdx.x >> 6;
    int d = c*64 + dl;
    size_t base = (size_t)b*Llen*DM_ + d;
    float s = 0.f;
    for (int t = tp; t < Llen; t += 4) s += Y[base + (size_t)t*DM_];
    __shared__ float red[4][64];
    red[tp][dl] = s; __syncthreads();
    if (tp == 0) red[0][dl] = (red[0][dl]+red[1][dl]+red[2][dl]+red[3][dl]) / (float)Llen;
    __syncthreads();
    float m = red[0][dl];
    for (int t = tp; t < Llen; t += 4) {
        size_t idx = base + (size_t)t*DM_;
        float v = Y[idx] - m;
        Y[idx] = v;
        if (H) {
            bf h = __float2bfloat16(v);
            H[idx] = h; L[idx] = __float2bfloat16(v - __bfloat162float(h));
        }
    }
}

__global__ void k_final(const float* __restrict__ XLN, const float* __restrict__ TS,
                        const float* __restrict__ meanb, const float* __restrict__ Wt,
                        const float* __restrict__ Wp, const float* __restrict__ bp,
                        float* __restrict__ out) {
    int p = blockIdx.x, b = blockIdx.y, tid = threadIdx.x;
    int t = LBL_ + p;
    int r0 = (t - 1 + LD_) % LD_;
    int r2 = (t + 1) % LD_;
    float acc[NC_];
    #pragma unroll
    for (int c = 0; c < NC_; c++) acc[c] = 0.f;
    for (int d = tid; d < DM_; d += 256) {
        float xv  = XLN[((size_t)b*LD_ + t )*DM_ + d];
        float tv0 = TS [((size_t)b*LD_ + r0)*DM_ + d];
        float tv1 = TS [((size_t)b*LD_ + t )*DM_ + d];
        float tv2 = TS [((size_t)b*LD_ + r2)*DM_ + d];
        #pragma unroll
        for (int c = 0; c < NC_; c++) {
            acc[c] += xv  * Wp[(size_t)d*NC_ + c]
                    + tv0 * Wt[((size_t)0*DM_ + d)*NC_ + c]
                    + tv1 * Wt[((size_t)1*DM_ + d)*NC_ + c]
                    + tv2 * Wt[((size_t)2*DM_ + d)*NC_ + c];
        }
    }
    __shared__ float red[256];
    for (int c = 0; c < NC_; c++) {
        red[tid] = acc[c]; __syncthreads();
        for (int st = 128; st > 0; st >>= 1) { if (tid < st) red[tid] += red[tid+st]; __syncthreads(); }
        if (tid == 0)
            out[((size_t)b*PRED_ + p)*NC_ + c] = red[0] + meanb[b*NC_ + c] + bp[c];
        __syncthreads();
    }
}

// ================= host orchestration =================
static bf *ABH, *ABL, *QBH, *QBL, *KBH, *KBL, *HBH, *HBL, *WBH, *WBL;
static bf *DBH, *DBL, *DQH, *DQL, *DKH, *DKL;

extern "C" void kernel_launch(void* const* d_in, const int* in_sizes, int n_in,
                              void* d_out, int out_size) {
    const float* x_enc      = (const float*)d_in[0];
    const float* x_mark_enc = (const float*)d_in[1];
    const float* x_mark_dec = (const float*)d_in[3];
    const float* W_enc_emb  = (const float*)d_in[4];
    const float* W_mark_enc = (const float*)d_in[5];
    const float* W_dec_emb  = (const float*)d_in[6];
    const float* W_mark_dec = (const float*)d_in[7];
    const float* eW_attn    = (const float*)d_in[8];
    const float* eb_attn    = (const float*)d_in[9];
    const float* eW1        = (const float*)d_in[10];
    const float* eW2        = (const float*)d_in[11];
    const float* eg         = (const float*)d_in[12];
    const float* ebeta      = (const float*)d_in[13];
    const float* sW         = (const float*)d_in[14];
    const float* sb         = (const float*)d_in[15];
    const float* cW         = (const float*)d_in[16];
    const float* cb         = (const float*)d_in[17];
    const float* dW1        = (const float*)d_in[18];
    const float* dW2        = (const float*)d_in[19];
    const float* W_trend    = (const float*)d_in[20];
    const float* dg         = (const float*)d_in[21];
    const float* dbeta      = (const float*)d_in[22];
    const float* Wproj      = (const float*)d_in[23];
    const float* bproj      = (const float*)d_in[24];
    float* out = (float*)d_out;

    static cudaStream_t s2 = nullptr;
    static cudaEvent_t ev0 = nullptr, ev1 = nullptr;
    if (!s2) {
        cudaStreamCreateWithFlags(&s2, cudaStreamNonBlocking);
        cudaEventCreateWithFlags(&ev0, cudaEventDisableTiming);
        cudaEventCreateWithFlags(&ev1, cudaEventDisableTiming);
    }

    cudaFuncSetAttribute(k_mma, cudaFuncAttributeMaxDynamicSharedMemorySize, SMEM_SZ);

    float* ws = nullptr;   cudaGetSymbolAddress((void**)&ws, g_ws);
    float* dws = nullptr;  cudaGetSymbolAddress((void**)&dws, g_dws);
    int* dly = nullptr;    cudaGetSymbolAddress((void**)&dly, g_delay);
    int* dly2 = nullptr;   cudaGetSymbolAddress((void**)&dly2, g_delay2);
    cudaGetSymbolAddress((void**)&ABH, g_abh);
    cudaGetSymbolAddress((void**)&ABL, g_abl);
    cudaGetSymbolAddress((void**)&QBH, g_qbh);
    cudaGetSymbolAddress((void**)&QBL, g_qbl);
    cudaGetSymbolAddress((void**)&KBH, g_kbh);
    cudaGetSymbolAddress((void**)&KBL, g_kbl);
    cudaGetSymbolAddress((void**)&HBH, g_hbh);
    cudaGetSymbolAddress((void**)&HBL, g_hbl);
    cudaGetSymbolAddress((void**)&WBH, g_wbh);
    cudaGetSymbolAddress((void**)&WBL, g_wbl);
    cudaGetSymbolAddress((void**)&DBH, g_dbh);
    cudaGetSymbolAddress((void**)&DBL, g_dbl);
    cudaGetSymbolAddress((void**)&DQH, g_dqh);
    cudaGetSymbolAddress((void**)&DQL, g_dql);
    cudaGetSymbolAddress((void**)&DKH, g_dkh);
    cudaGetSymbolAddress((void**)&DKL, g_dkl);

    float* XE   = ws + O_XE;
    float* XA   = ws + O_XA;
    float* XD   = ws + O_XD;
    float* Qb   = ws + O_Q;
    float* Vb   = ws + O_V;
    float* Tb   = ws + O_T;
    float* Gb   = ws + O_G;
    float* CORR = ws + O_CORR;
    float* ENC  = ws + O_ENC;
    float* TS   = ws + O_TS;
    float* SEA  = ws + O_SEA;
    float* MEANB= ws + O_MEAN;
    float* WGT  = ws + O_WGT;
    float* dT    = dws + OD_T;
    float* dG    = dws + OD_G;
    float* dCORR = dws + OD_CORR;
    float* dWGT  = dws + OD_WGT;

    // weights first (both streams need them), then fork
    k_cvtT_all<<<10240, dim3(32,8)>>>(eW_attn, eW1, eW2, sW, cW, dW1, dW2, WBH, WBL);
    cudaEventRecord(ev0, 0);
    cudaStreamWaitEvent(s2, ev0, 0);

    // ======== stream B: decoder self-attention chain ========
    k_sea<<<(B_*LE_*NC_ + 255)/256, 256, 0, s2>>>(x_enc, SEA);
    k_embed_dec2<<<dim3((LD_+31)/32, B_, 2), 256, 0, s2>>>(SEA, x_mark_enc, x_mark_dec,
                                                           W_dec_emb, W_mark_dec, XD, DBH, DBL);
    {
        int n = B_*(LP_-LD_)*DM_;
        k_padzero<<<(n+255)/256, 256, 0, s2>>>(DQH, DQL, LD_);
        k_padzero<<<(n+255)/256, 256, 0, s2>>>(DKH, DKL, LD_);
    }
    k_mma<<<dim3(12,148,1), 256, SMEM_SZ, s2>>>(DBH, DBL, DM_, WBH+OW_SW, WBL+OW_SW, DM_,
        DM_, B_*LD_, 1536, 0, 0, 0,
        2, Qb, DM_, DQH, DQL, 0, DKH, DKL, LD_, LP_, 4, 4, nullptr, sb, 0);
    k_mma<<<dim3(5,5,B_), 256, SMEM_SZ, s2>>>(DQH, DQL, DM_, DKH, DKL, DM_,
        DM_, LD_, LD_, (long long)LP_*DM_, (long long)LP_*DM_, (long long)LD_*LD_,
        0, dG, LD_, nullptr, nullptr, 0, nullptr, nullptr, LD_, LD_, 0, 0, nullptr, nullptr, 0);
    k_zero<<<(B_*LD_ + 255)/256, 256, 0, s2>>>(dCORR, B_*LD_);
    k_corr2<<<dim3((LD_+15)/16, B_), 256, 0, s2>>>(dG, dCORR, LD_, LD_*LD_);
    k_topk<<<B_, 256, 0, s2>>>(dCORR, LD_, KT_D, dly2, dWGT);
    k_agg<<<dim3(LD_, B_), DM_, 0, s2>>>(Qb, DM_, dly2, dWGT, DBH, DBL,
                                         LD_, LD_, KT_D, (long long)LD_*DM_);
    k_mma<<<dim3(4,148,1), 256, SMEM_SZ, s2>>>(DBH, DBL, DM_,
        WBH+OW_SW+3*(size_t)DM_*DM_, WBL+OW_SW+3*(size_t)DM_*DM_, DM_,
        DM_, B_*LD_, DM_, 0, 0, 0,
        0, dT, DM_, nullptr, nullptr, 0, nullptr, nullptr, LD_, LD_, 0, 0, XD, sb+3*DM_, 0);
    k_add_decomp2<<<dim3(8, B_), DM_, 0, s2>>>(dT, XD, TS, DBH, DBL, LD_, 1);
    cudaEventRecord(ev1, s2);

    // ======== stream 0: encoder ========
    k_meanc<<<B_, 256>>>(x_enc, MEANB);
    k_embed_enc2<<<dim3(LE_/32, B_, 2), 256>>>(x_enc, x_mark_enc, W_enc_emb, W_mark_enc, XE, ABH, ABL);

    float* x = XE;
    for (int l = 0; l < 2; l++) {
        const float* bb = eb_attn + (size_t)l*4*DM_;
        size_t wa = OW_EATT + (size_t)l*4*DM_*DM_;
        k_mma<<<dim3(12,128,1), 256, SMEM_SZ>>>(ABH, ABL, DM_, WBH+wa, WBL+wa, DM_,
            DM_, B_*LE_, 1536, 0, 0, 0,
            2, Vb, DM_, QBH, QBL, 0, KBH, KBL, LE_, LE_, 4, 4, nullptr, bb, 0);
        k_mma<<<dim3(4,4,B_), 256, SMEM_SZ>>>(QBH, QBL, DM_, KBH, KBL, DM_,
            DM_, LE_, LE_, (long long)LE_*DM_, (long long)LE_*DM_, (long long)LE_*LE_,
            0, Gb, LE_, nullptr, nullptr, 0, nullptr, nullptr, LE_, LE_, 0, 0, nullptr, nullptr, 0);
        k_zero<<<(B_*LE_ + 255)/256, 256>>>(CORR, B_*LE_);
        k_corr2<<<dim3(LE_/16, B_), 256>>>(Gb, CORR, LE_, LE_*LE_);
        k_topk<<<B_, 256>>>(CORR, LE_, KT_E, dly, WGT);
        k_agg<<<dim3(LE_, B_), DM_>>>(Vb, DM_, dly, WGT, ABH, ABL,
                                      LE_, LE_, KT_E, (long long)LE_*DM_);
        k_mma<<<dim3(4,128,1), 256, SMEM_SZ>>>(ABH, ABL, DM_,
            WBH+wa+3*(size_t)DM_*DM_, WBL+wa+3*(size_t)DM_*DM_, DM_,
            DM_, B_*LE_, DM_, 0, 0, 0,
            0, Tb, DM_, nullptr, nullptr, 0, nullptr, nullptr, LE_, LE_, 0, 0, x, bb+3*DM_, 0);
        float* nx = (x == XE) ? XA : XE;
        k_add_decomp2<<<dim3(8, B_), DM_>>>(Tb, nx, nullptr, ABH, ABL, LE_, 0);
        x = nx;
        k_mma<<<dim3(16,128,1), 256, SMEM_SZ>>>(ABH, ABL, DM_,
            WBH+OW_EW1+(size_t)l*DM_*DFF_, WBL+OW_EW1+(size_t)l*DM_*DFF_, DM_,
            DM_, B_*LE_, DFF_, 0, 0, 0,
            1, nullptr, 0, HBH, HBL, DFF_, nullptr, nullptr, LE_, LE_, 0, 0, nullptr, nullptr, 1);
        k_mma<<<dim3(4,128,1), 256, SMEM_SZ>>>(HBH, HBL, DFF_,
            WBH+OW_EW2+(size_t)l*DFF_*DM_, WBL+OW_EW2+(size_t)l*DFF_*DM_, DFF_,
            DFF_, B_*LE_, DM_, 0, 0, 0,
            0, Tb, DM_, nullptr, nullptr, 0, nullptr, nullptr, LE_, LE_, 0, 0, x, nullptr, 0);
        nx = (x == XE) ? XA : XE;
        k_add_decomp2<<<dim3(8, B_), DM_>>>(Tb, nx, nullptr, ABH, ABL, LE_, 0);
        x = nx;
    }
    k_ln<<<B_*LE_, 256>>>(x, eg, ebeta, ENC);
    k_submean2<<<B_*8, 256>>>(ENC, HBH, HBL, LE_);

    // ---- join ----
    cudaStreamWaitEvent(0, ev1, 0);

    // cross attention: Q from dec-x split (DBH/DBL), K/V from ENC split (HBH/HBL)
    k_mma<<<dim3(4,148,1), 256, SMEM_SZ>>>(DBH, DBL, DM_, WBH+OW_CW, WBL+OW_CW, DM_,
        DM_, B_*LD_, DM_, 0, 0, 0,
        1, nullptr, 0, DQH, DQL, DM_, nullptr, nullptr, LD_, LP_, 0, 0, nullptr, cb, 0);
    {
        int n = B_*(LP_-LE_)*DM_;
        k_padzero<<<(n+255)/256, 256>>>(KBH, KBL, LE_);
    }
    k_mma<<<dim3(8,128,1), 256, SMEM_SZ>>>(HBH, HBL, DM_,
        WBH+OW_CW+(size_t)DM_*DM_, WBL+OW_CW+(size_t)DM_*DM_, DM_,
        DM_, B_*LE_, 1024, 0, 0, 0,
        3, Vb, DM_, nullptr, nullptr, 0, KBH, KBL, LE_, LP_, 0, 4, nullptr, cb+DM_, 0);
    k_mma<<<dim3(5,5,B_), 256, SMEM_SZ>>>(DQH, DQL, DM_, KBH, KBL, DM_,
        DM_, LD_, LD_, (long long)LP_*DM_, (long long)LP_*DM_, (long long)LD_*LD_,
        0, Gb, LD_, nullptr, nullptr, 0, nullptr, nullptr, LD_, LD_, 0, 0, nullptr, nullptr, 0);
    k_zero<<<(B_*LD_ + 255)/256, 256>>>(CORR, B_*LD_);
    k_corr2<<<dim3((LD_+15)/16, B_), 256>>>(Gb, CORR, LD_, LD_*LD_);
    k_topk<<<B_, 256>>>(CORR, LD_, KT_D, dly, WGT);
    k_agg<<<dim3(LD_, B_), DM_>>>(Vb, DM_, dly, WGT, ABH, ABL,
                                  LD_, LE_, KT_D, (long long)LE_*DM_);
    k_mma<<<dim3(4,148,1), 256, SMEM_SZ>>>(ABH, ABL, DM_,
        WBH+OW_CW+3*(size_t)DM_*DM_, WBL+OW_CW+3*(size_t)DM_*DM_, DM_,
        DM_, B_*LD_, DM_, 0, 0, 0,
        0, Tb, DM_, nullptr, nullptr, 0, nullptr, nullptr, LD_, LD_, 0, 0, XD, cb+3*DM_, 0);
    k_add_decomp2<<<dim3(8, B_), DM_>>>(Tb, XE, TS, ABH, ABL, LD_, 2);

    // FFN
    k_mma<<<dim3(16,148,1), 256, SMEM_SZ>>>(ABH, ABL, DM_,
        WBH+OW_DW1, WBL+OW_DW1, DM_,
        DM_, B_*LD_, DFF_, 0, 0, 0,
        1, nullptr, 0, HBH, HBL, DFF_, nullptr, nullptr, LD_, LD_, 0, 0, nullptr, nullptr, 1);
    k_mma<<<dim3(4,148,1), 256, SMEM_SZ>>>(HBH, HBL, DFF_,
        WBH+OW_DW2, WBL+OW_DW2, DFF_,
        DFF_, B_*LD_, DM_, 0, 0, 0,
        0, Tb, DM_, nullptr, nullptr, 0, nullptr, nullptr, LD_, LD_, 0, 0, XE, nullptr, 0);
    k_add_decomp2<<<dim3(8, B_), DM_>>>(Tb, XA, TS, ABH, ABL, LD_, 2);

    // final layernorm + output assembly
    k_ln<<<B_*LD_, 256>>>(XA, dg, dbeta, Qb);
    k_submean2<<<B_*8, 256>>>(Qb, nullptr, nullptr, LD_);
    k_final<<<dim3(PRED_, B_), 256>>>(Qb, TS, MEANB, W_trend, Wproj, bproj, out);
}

// round 14
// speedup vs baseline: 1.0665x; 1.0073x over previous
#include <cuda_runtime.h>
#include <cuda_bf16.h>
#include <math.h>
#include <float.h>
#include <stdint.h>

typedef __nv_bfloat16 bf;

#define B_    32
#define LE_   512
#define LD_   592
#define LP_   640
#define DM_   512
#define DFF_  2048
#define NC_   7
#define NM_   4
#define LBL_  256
#define PRED_ 336
#define KT_E  18
#define KT_D  19

#define SZ_XE  ((size_t)B_*LE_*DM_)
#define SZ_XD  ((size_t)B_*LD_*DM_)
#define SZ_G   ((size_t)B_*LD_*LD_)

#define O_XE   ((size_t)0)
#define O_XA   (O_XE + SZ_XE)
#define O_XD   (O_XA + SZ_XD)
#define O_Q    (O_XD + SZ_XD)
#define O_V    (O_Q  + SZ_XD)
#define O_T    (O_V  + SZ_XD)
#define O_G    (O_T  + SZ_XD)
#define O_CORR (O_G  + SZ_G)
#define O_ENC  (O_CORR + (size_t)B_*LD_)
#define O_TS   (O_ENC + SZ_XE)
#define O_SEA  (O_TS + SZ_XD)
#define O_MEAN (O_SEA + (size_t)B_*LE_*NC_)
#define O_WGT  (O_MEAN + (size_t)B_*NC_)
#define WS_TOTAL (O_WGT + (size_t)B_*32)

__device__ __align__(256) float g_ws[WS_TOTAL];
__device__ int g_delay[B_*32];
__device__ int g_delay2[B_*32];

#define OD_T   ((size_t)0)
#define OD_G   (OD_T + SZ_XD)
#define OD_CORR (OD_G + SZ_G)
#define OD_WGT (OD_CORR + (size_t)B_*LD_)
#define DWS_TOTAL (OD_WGT + (size_t)B_*32)
__device__ __align__(256) float g_dws[DWS_TOTAL];

#define SZ_AB  ((size_t)B_*LP_*DM_)
#define SZ_QB  ((size_t)B_*LP_*DM_)
#define SZ_KB  ((size_t)B_*LP_*DM_)
#define SZ_HB  ((size_t)B_*LD_*DFF_)
#define OW_EATT ((size_t)0)
#define OW_EW1  ((size_t)2097152)
#define OW_EW2  ((size_t)4194304)
#define OW_SW   ((size_t)6291456)
#define OW_CW   ((size_t)7340032)
#define OW_DW1  ((size_t)8388608)
#define OW_DW2  ((size_t)9437184)
#define SZ_WB   ((size_t)10485760)

__device__ __align__(256) bf g_abh[SZ_AB];
__device__ __align__(256) bf g_abl[SZ_AB];
__device__ __align__(256) bf g_qbh[SZ_QB];
__device__ __align__(256) bf g_qbl[SZ_QB];
__device__ __align__(256) bf g_kbh[SZ_KB];
__device__ __align__(256) bf g_kbl[SZ_KB];
__device__ __align__(256) bf g_hbh[SZ_HB];
__device__ __align__(256) bf g_hbl[SZ_HB];
__device__ __align__(256) bf g_wbh[SZ_WB];
__device__ __align__(256) bf g_wbl[SZ_WB];
__device__ __align__(256) bf g_dbh[SZ_AB];
__device__ __align__(256) bf g_dbl[SZ_AB];
__device__ __align__(256) bf g_dqh[SZ_QB];
__device__ __align__(256) bf g_dql[SZ_QB];
__device__ __align__(256) bf g_dkh[SZ_KB];
__device__ __align__(256) bf g_dkl[SZ_KB];

__device__ __forceinline__ float gelu_exact(float v) {
    return 0.5f * v * (1.0f + erff(v * 0.70710678118654752440f));
}
__device__ __forceinline__ uint32_t s2u(const void* p){
    uint32_t a;
    asm("{ .reg .u64 t; cvta.to.shared.u64 t, %1; cvt.u32.u64 %0, t; }":"=r"(a):"l"(p));
    return a;
}
#define SWZ(o) ((o) ^ (((o)>>3)&0x70))

#define LDSM4(r, ad) \
    asm volatile("ldmatrix.sync.aligned.m8n8.x4.shared.b16 {%0,%1,%2,%3}, [%4];" \
        : "=r"((r)[0]), "=r"((r)[1]), "=r"((r)[2]), "=r"((r)[3]) : "r"(ad))

#define MMA16816(d, a, b0, b1) \
    asm volatile("mma.sync.aligned.m16n8k16.row.col.f32.bf16.bf16.f32 " \
        "{%0,%1,%2,%3}, {%4,%5,%6,%7}, {%8,%9}, {%0,%1,%2,%3};" \
        : "+f"((d)[0]), "+f"((d)[1]), "+f"((d)[2]), "+f"((d)[3]) \
        : "r"((a)[0]), "r"((a)[1]), "r"((a)[2]), "r"((a)[3]), "r"(b0), "r"(b1))

__device__ __forceinline__ void split_store(bf* H, bf* L, size_t o, float v0, float v1){
    bf h0 = __float2bfloat16(v0), h1 = __float2bfloat16(v1);
    bf l0 = __float2bfloat16(v0 - __bfloat162float(h0));
    bf l1 = __float2bfloat16(v1 - __bfloat162float(h1));
    *(__nv_bfloat162*)(H + o) = __nv_bfloat162(h0, h1);
    *(__nv_bfloat162*)(L + o) = __nv_bfloat162(l0, l1);
}

__global__ void k_cvtT_all(const float* __restrict__ eatt, const float* __restrict__ e1,
                           const float* __restrict__ e2, const float* __restrict__ sw,
                           const float* __restrict__ cw, const float* __restrict__ d1,
                           const float* __restrict__ d2,
                           bf* __restrict__ WH, bf* __restrict__ WL){
    __shared__ float t[32][33];
    int blk = blockIdx.x;
    const float* src; size_t dstoff; int K, N, mi, tt;
    if (blk < 2048)       { src=eatt; dstoff=OW_EATT; K=512; N=512;  mi=blk/256;        tt=blk%256; }
    else if (blk < 4096)  { src=e1;   dstoff=OW_EW1;  K=512; N=2048; mi=(blk-2048)/1024; tt=(blk-2048)%1024; }
    else if (blk < 6144)  { src=e2;   dstoff=OW_EW2;  K=2048;N=512;  mi=(blk-4096)/1024; tt=(blk-4096)%1024; }
    else if (blk < 7168)  { src=sw;   dstoff=OW_SW;   K=512; N=512;  mi=(blk-6144)/256;  tt=(blk-6144)%256; }
    else if (blk < 8192)  { src=cw;   dstoff=OW_CW;   K=512; N=512;  mi=(blk-7168)/256;  tt=(blk-7168)%256; }
    else if (blk < 9216)  { src=d1;   dstoff=OW_DW1;  K=512; N=2048; mi=0;               tt=blk-8192; }
    else                  { src=d2;   dstoff=OW_DW2;  K=2048;N=512;  mi=0;               tt=blk-9216; }
    int tn = N/32;
    int n0 = (tt % tn)*32, k0 = (tt / tn)*32;
    const float* W = src + (size_t)mi*K*N;
    bf* TH = WH + dstoff + (size_t)mi*K*N;
    bf* TL = WL + dstoff + (size_t)mi*K*N;
    int tx = threadIdx.x, ty = threadIdx.y;
    #pragma unroll
    for (int i = 0; i < 32; i += 8)
        t[ty+i][tx] = W[(size_t)(k0+ty+i)*N + n0 + tx];
    __syncthreads();
    #pragma unroll
    for (int i = 0; i < 32; i += 8) {
        float x = t[tx][ty+i];
        bf h = __float2bfloat16(x);
        size_t o = (size_t)(n0+ty+i)*K + k0 + tx;
        TH[o] = h; TL[o] = __float2bfloat16(x - __bfloat162float(h));
    }
}

#define SMEM_SZ 131072

__device__ __forceinline__ void ldchunk(uint32_t st,
    const bf* __restrict__ A_h, const bf* __restrict__ A_l, int lda,
    const bf* __restrict__ B_h, const bf* __restrict__ B_l, int ldb,
    int k0, int tid)
{
    const bf* srcs[4] = {A_h, A_l, B_h, B_l};
    const int lds[4] = {lda, lda, ldb, ldb};
    #pragma unroll
    for (int t = 0; t < 4; t++) {
        #pragma unroll
        for (int i = 0; i < 4; i++) {
            int idx = i*256 + tid;
            int row = idx >> 3, c16 = idx & 7;
            uint32_t dst = st + t*16384 + SWZ(row*128 + c16*16);
            const bf* src = srcs[t] + (size_t)row*lds[t] + k0 + c16*8;
            asm volatile("cp.async.cg.shared.global [%0], [%1], 16;\n"::"r"(dst),"l"(src));
        }
    }
    asm volatile("cp.async.commit_group;\n":::"memory");
}

__global__ void __launch_bounds__(256,1) k_mma(
    const bf* __restrict__ Ah, const bf* __restrict__ Al, int lda,
    const bf* __restrict__ Bh, const bf* __restrict__ Bl, int ldb,
    int K, int rowsV, int colsV,
    long long aB, long long bB, long long cB,
    int mode, float* __restrict__ C, int ldc,
    bf* __restrict__ H0, bf* __restrict__ L0, int ldh0,
    bf* __restrict__ H1, bf* __restrict__ L1,
    int Lv, int Lp, int nq, int nk,
    const float* __restrict__ RES, const float* __restrict__ bias, int act)
{
    extern __shared__ char smem[];
    uint32_t sb0 = s2u(smem);
    const int tid = threadIdx.x, lane = tid & 31, wid = tid >> 5;
    const int bn = blockIdx.x, bm = blockIdx.y, bz = blockIdx.z;
    const bf* Ah2 = Ah + (size_t)bz*aB + (size_t)bm*128*lda;
    const bf* Al2 = Al + (size_t)bz*aB + (size_t)bm*128*lda;
    const bf* Bh2 = Bh + (size_t)bz*bB + (size_t)bn*128*ldb;
    const bf* Bl2 = Bl + (size_t)bz*bB + (size_t)bn*128*ldb;
    if (C) C += (size_t)bz*cB;

    float acc[4][4][4];
    #pragma unroll
    for (int i = 0; i < 4; i++)
        #pragma unroll
        for (int j = 0; j < 4; j++)
            #pragma unroll
            for (int q = 0; q < 4; q++) acc[i][j][q] = 0.f;

    const int KC = K >> 6;
    const int m0 = (wid & 1) << 6, n0 = (wid >> 1) << 5;

    ldchunk(sb0, Ah2, Al2, lda, Bh2, Bl2, ldb, 0, tid);

    for (int c = 0; c < KC; c++) {
        uint32_t st = sb0 + (uint32_t)(c & 1) * 65536u;
        if (c+1 < KC) {
            ldchunk(sb0 + (uint32_t)((c+1) & 1) * 65536u,
                    Ah2, Al2, lda, Bh2, Bl2, ldb, (c+1)*64, tid);
            asm volatile("cp.async.wait_group 1;\n":::"memory");
        } else {
            asm volatile("cp.async.wait_group 0;\n":::"memory");
        }
        __syncthreads();

        #pragma unroll
        for (int kk = 0; kk < 4; kk++) {
            uint32_t afh[4][4], afl[4][4], bfh[2][4], bfl[2][4];
            #pragma unroll
            for (int mt = 0; mt < 4; mt++) {
                int m = m0 + mt*16 + (lane & 15);
                int kb = kk*32 + ((lane >> 4) << 4);
                uint32_t off = SWZ(m*128 + kb);
                LDSM4(afh[mt], st + off);
                LDSM4(afl[mt], st + 16384u + off);
            }
            #pragma unroll
            for (int nt2 = 0; nt2 < 2; nt2++) {
                int g = lane >> 3;
                int n = n0 + nt2*16 + ((g >> 1) << 3) + (lane & 7);
                int kb = kk*32 + ((g & 1) << 4);
                uint32_t off = SWZ(n*128 + kb);
                LDSM4(bfh[nt2], st + 32768u + off);
                LDSM4(bfl[nt2], st + 49152u + off);
            }
            #pragma unroll
            for (int mt = 0; mt < 4; mt++)
                #pragma unroll
                for (int nt = 0; nt < 4; nt++)
                    MMA16816(acc[mt][nt], afh[mt],
                             bfh[nt>>1][(nt&1)*2], bfh[nt>>1][(nt&1)*2+1]);
            #pragma unroll
            for (int mt = 0; mt < 4; mt++)
                #pragma unroll
                for (int nt = 0; nt < 4; nt++)
                    MMA16816(acc[mt][nt], afh[mt],
                             bfl[nt>>1][(nt&1)*2], bfl[nt>>1][(nt&1)*2+1]);
            #pragma unroll
            for (int mt = 0; mt < 4; mt++)
                #pragma unroll
                for (int nt = 0; nt < 4; nt++)
                    MMA16816(acc[mt][nt], afl[mt],
                             bfh[nt>>1][(nt&1)*2], bfh[nt>>1][(nt&1)*2+1]);
        }
        __syncthreads();
    }

    const int gid = lane >> 2, tig = lane & 3;
    const int nq128 = nq*128, nqk128 = (nq+nk)*128;
    #pragma unroll
    for (int mt = 0; mt < 4; mt++) {
        #pragma unroll
        for (int h = 0; h < 2; h++) {
            int row = bm*128 + m0 + mt*16 + gid + h*8;
            if (row >= rowsV) continue;
            int bq = row / Lv, rr = row - bq*Lv;
            size_t prow = (size_t)bq*Lp + rr;
            #pragma unroll
            for (int nt = 0; nt < 4; nt++) {
                int col = bn*128 + n0 + nt*8 + tig*2;
                if (col >= colsV) continue;
                float v0 = acc[mt][nt][h*2+0];
                float v1 = acc[mt][nt][h*2+1];
                if (bias) { v0 += bias[col]; v1 += bias[col+1]; }
                if (act)  { v0 = gelu_exact(v0); v1 = gelu_exact(v1); }
                if (mode == 0) {
                    size_t o = (size_t)row*ldc + col;
                    if (RES) { float2 r2 = *(const float2*)(RES + o); v0 += r2.x; v1 += r2.y; }
                    *(float2*)(C + o) = make_float2(v0, v1);
                } else if (mode == 1) {
                    split_store(H0, L0, prow*ldh0 + col, v0, v1);
                } else {
                    if (col < nq128)
                        split_store(H0, L0, prow*DM_ + col, v0, v1);
                    else if (col < nqk128)
                        split_store(H1, L1, prow*DM_ + (col - nq128), v0, v1);
                    else
                        *(float2*)(C + (size_t)row*ldc + (col - nqk128)) = make_float2(v0, v1);
                }
            }
        }
    }
}

__global__ void k_sea(const float* __restrict__ xe, float* __restrict__ sea) {
    int i = blockIdx.x * blockDim.x + threadIdx.x;
    if (i >= B_*LE_*NC_) return;
    int c = i % NC_;
    int t = (i / NC_) % LE_;
    int b = i / (NC_*LE_);
    float s = 0.f;
    #pragma unroll
    for (int j = -12; j <= 12; j++) {
        int tt = t + j; tt = tt < 0 ? 0 : (tt >= LE_ ? LE_-1 : tt);
        s += xe[((size_t)b*LE_ + tt)*NC_ + c];
    }
    sea[i] = xe[i] - s * (1.0f/25.0f);
}

__global__ void k_meanc(const float* __restrict__ xe, float* __restrict__ mb) {
    int b = blockIdx.x, tid = threadIdx.x;
    __shared__ float red[7][32];
    if (tid < 224) {
        int c = tid % NC_, slot = tid / NC_;
        float s = 0.f;
        for (int t = slot; t < LE_; t += 32) s += xe[((size_t)b*LE_ + t)*NC_ + c];
        red[c][slot] = s;
    }
    __syncthreads();
    if (tid < NC_) {
        float s = 0.f;
        #pragma unroll
        for (int j = 0; j < 32; j++) s += red[tid][j];
        mb[b*NC_ + tid] = s * (1.0f/LE_);
    }
}

__global__ void k_embed_enc2(const float* __restrict__ xe, const float* __restrict__ mk,
                             const float* __restrict__ Wemb, const float* __restrict__ Wm,
                             float* __restrict__ out, bf* __restrict__ H, bf* __restrict__ Lo) {
    int tc = blockIdx.x, b = blockIdx.y, dh = blockIdx.z;
    int tid = threadIdx.x;
    int d = dh*256 + tid;
    __shared__ float sw[25][256];
    __shared__ float sx[34][NC_];
    __shared__ float sm[32][NM_];
    for (int i = tid; i < 21*256; i += 256) {
        int j = i >> 8, dd = i & 255;
        sw[j][dd] = Wemb[(size_t)j*DM_ + dh*256 + dd];
    }
    for (int i = tid; i < 4*256; i += 256) {
        int m = i >> 8, dd = i & 255;
        sw[21+m][dd] = Wm[(size_t)m*DM_ + dh*256 + dd];
    }
    int t0 = tc*32;
    for (int i = tid; i < 34*NC_; i += 256) {
        int rr = i / NC_, c = i % NC_;
        int r = (t0 - 1 + rr + LE_) % LE_;
        sx[rr][c] = xe[((size_t)b*LE_ + r)*NC_ + c];
    }
    for (int i = tid; i < 32*NM_; i += 256) {
        int rr = i / NM_, m = i % NM_;
        sm[rr][m] = mk[((size_t)b*LE_ + t0 + rr)*NM_ + m];
    }
    __syncthreads();
    for (int tt = 0; tt < 32; tt++) {
        float acc = 0.f;
        #pragma unroll
        for (int j = 0; j < 3; j++)
            #pragma unroll
            for (int c = 0; c < NC_; c++)
                acc += sx[tt + j][c] * sw[j*NC_ + c][tid];
        #pragma unroll
        for (int m = 0; m < NM_; m++) acc += sm[tt][m] * sw[21+m][tid];
        size_t o = ((size_t)b*LE_ + t0 + tt)*DM_ + d;
        out[o] = acc;
        bf h = __float2bfloat16(acc);
        H[o] = h; Lo[o] = __float2bfloat16(acc - __bfloat162float(h));
    }
}

__global__ void k_embed_dec2(const float* __restrict__ sea, const float* __restrict__ mk_enc,
                             const float* __restrict__ mk_dec,
                             const float* __restrict__ Wemb, const float* __restrict__ Wm,
                             float* __restrict__ out, bf* __restrict__ H, bf* __restrict__ Lo) {
    int tc = blockIdx.x, b = blockIdx.y, dh = blockIdx.z;
    int tid = threadIdx.x;
    int d = dh*256 + tid;
    __shared__ float sw[25][256];
    __shared__ float sx[34][NC_];
    __shared__ float sm[32][NM_];
    for (int i = tid; i < 21*256; i += 256) {
        int j = i >> 8, dd = i & 255;
        sw[j][dd] = Wemb[(size_t)j*DM_ + dh*256 + dd];
    }
    for (int i = tid; i < 4*256; i += 256) {
        int m = i >> 8, dd = i & 255;
        sw[21+m][dd] = Wm[(size_t)m*DM_ + dh*256 + dd];
    }
    int t0 = tc*32;
    for (int i = tid; i < 34*NC_; i += 256) {
        int rr = i / NC_, c = i % NC_;
        int r = (t0 - 1 + rr + LD_) % LD_;
        sx[rr][c] = (r < LBL_) ? sea[((size_t)b*LE_ + LBL_ + r)*NC_ + c] : 0.f;
    }
    for (int i = tid; i < 32*NM_; i += 256) {
        int rr = i / NM_, m = i % NM_;
        int t = t0 + rr;
        float v = 0.f;
        if (t < LD_) {
            v = (t < LBL_) ? mk_enc[((size_t)b*LE_ + LBL_ + t)*NM_ + m]
                           : mk_dec[((size_t)b*PRED_ + (t - LBL_))*NM_ + m];
        }
        sm[rr][m] = v;
    }
    __syncthreads();
    for (int tt = 0; tt < 32; tt++) {
        int t = t0 + tt;
        if (t >= LD_) break;
        float acc = 0.f;
        #pragma unroll
        for (int j = 0; j < 3; j++)
            #pragma unroll
            for (int c = 0; c < NC_; c++)
                acc += sx[tt + j][c] * sw[j*NC_ + c][tid];
        #pragma unroll
        for (int m = 0; m < NM_; m++) acc += sm[tt][m] * sw[21+m][tid];
        size_t o = ((size_t)b*LD_ + t)*DM_ + d;
        out[o] = acc;
        bf h = __float2bfloat16(acc);
        H[o] = h; Lo[o] = __float2bfloat16(acc - __bfloat162float(h));
    }
}

// zero pad rows for two split buffer pairs at once
__global__ void k_padzero2(bf* __restrict__ H0, bf* __restrict__ L0,
                           bf* __restrict__ H1, bf* __restrict__ L1, int Lv){
    int span = LP_ - Lv;
    int n = B_*span*DM_;
    int i = blockIdx.x*256 + threadIdx.x;
    int which = 0;
    if (i >= n) { i -= n; which = 1; }
    if (i >= n) return;
    int d = i % DM_;
    int rr = (i / DM_) % span;
    int b = i / (DM_*span);
    size_t o = ((size_t)b*LP_ + Lv + rr)*DM_ + d;
    bf z = __float2bfloat16(0.f);
    if (which == 0) { H0[o] = z; L0[o] = z; }
    else            { H1[o] = z; L1[o] = z; }
}

__global__ void k_padzero(bf* __restrict__ H, bf* __restrict__ L, int Lv){
    int span = LP_ - Lv;
    int n = B_*span*DM_;
    int i = blockIdx.x*256 + threadIdx.x;
    if (i >= n) return;
    int d = i % DM_;
    int rr = (i / DM_) % span;
    int b = i / (DM_*span);
    size_t o = ((size_t)b*LP_ + Lv + rr)*DM_ + d;
    H[o] = __float2bfloat16(0.f);
    L[o] = __float2bfloat16(0.f);
}

__global__ void k_zero(float* __restrict__ p, int n){
    int i = blockIdx.x*256 + threadIdx.x;
    if (i < n) p[i] = 0.f;
}

__global__ void k_corr2(const float* __restrict__ G, float* __restrict__ corr,
                        int L, int gbs) {
    int b = blockIdx.y, tid = threadIdx.x;
    int t0 = blockIdx.x * 16;
    __shared__ float cs[640];
    for (int i = tid; i < L; i += 256) cs[i] = 0.f;
    __syncthreads();
    const float* Gb = G + (size_t)b*gbs;
    int t1 = min(t0 + 16, L);
    for (int t = t0; t < t1; t++) {
        const float* row = Gb + (size_t)t*L;
        for (int j = tid; j < L; j += 256) {
            int tau = t - j; if (tau < 0) tau += L;
            atomicAdd(&cs[tau], row[j]);
        }
    }
    __syncthreads();
    for (int i = tid; i < L; i += 256)
        atomicAdd(&corr[(size_t)b*L + i], cs[i] * (1.0f/DM_));
}

__global__ void k_topk(const float* __restrict__ corr, int L, int KT,
                       int* __restrict__ delay, float* __restrict__ wgt) {
    int b = blockIdx.x, tid = threadIdx.x;
    int lane = tid & 31, wid = tid >> 5;
    __shared__ float vals[640];
    __shared__ float wv[8];
    __shared__ int wi[8];
    __shared__ float tv[32];
    __shared__ int tix[32];
    for (int i = tid; i < L; i += 256) vals[i] = corr[(size_t)b*L + i];
    __syncthreads();
    for (int kt = 0; kt < KT; kt++) {
        float bv = -FLT_MAX; int bi = 0x7fffffff;
        for (int i = tid; i < L; i += 256) {
            float v = vals[i];
            if (v > bv || (v == bv && i < bi)) { bv = v; bi = i; }
        }
        #pragma unroll
        for (int o = 16; o > 0; o >>= 1) {
            float ov = __shfl_down_sync(0xffffffffu, bv, o);
            int   oi = __shfl_down_sync(0xffffffffu, bi, o);
            if (ov > bv || (ov == bv && oi < bi)) { bv = ov; bi = oi; }
        }
        if (lane == 0) { wv[wid] = bv; wi[wid] = bi; }
        __syncthreads();
        if (wid == 0) {
            float v2 = (lane < 8) ? wv[lane] : -FLT_MAX;
            int   i2 = (lane < 8) ? wi[lane] : 0x7fffffff;
            #pragma unroll
            for (int o = 4; o > 0; o >>= 1) {
                float ov = __shfl_down_sync(0xffffffffu, v2, o);
                int   oi = __shfl_down_sync(0xffffffffu, i2, o);
                if (ov > v2 || (ov == v2 && oi < i2)) { v2 = ov; i2 = oi; }
            }
            if (lane == 0) { tv[kt] = v2; tix[kt] = i2; vals[i2] = -FLT_MAX; }
        }
        __syncthreads();
    }
    if (tid == 0) {
        float mx = tv[0], s = 0.f;
        float e[32];
        for (int i = 0; i < KT; i++) { e[i] = expf(tv[i] - mx); s += e[i]; }
        float inv = 1.0f / s;
        for (int i = 0; i < KT; i++) {
            wgt[b*32 + i] = e[i] * inv;
            delay[b*32 + i] = tix[i];
        }
    }
}

__global__ void k_agg(const float* __restrict__ V, int vld, const int* __restrict__ delay,
                      const float* __restrict__ wgt, bf* __restrict__ OH,
                      bf* __restrict__ OL, int L, int S, int KT, long long vbs) {
    int t = blockIdx.x, b = blockIdx.y, d = threadIdx.x;
    __shared__ int sd[32];
    __shared__ float sw[32];
    if (d < KT) { sd[d] = delay[b*32 + d]; sw[d] = wgt[b*32 + d]; }
    __syncthreads();
    float acc = 0.f;
    for (int i = 0; i < KT; i++) {
        int r = t + sd[i]; if (r >= L) r -= L;
        if (r < S) acc += sw[i] * V[(size_t)b*vbs + (size_t)r*vld + d];
    }
    size_t o = ((size_t)b*L + t)*DM_ + d;
    bf h = __float2bfloat16(acc);
    OH[o] = h; OL[o] = __float2bfloat16(acc - __bfloat162float(h));
}

__global__ void k_add_decomp2(const float* __restrict__ R,
                              float* __restrict__ S, float* __restrict__ T,
                              bf* __restrict__ SH, bf* __restrict__ SL,
                              int L, int tmode) {
    int b = blockIdx.y, ch = blockIdx.x, d = threadIdx.x;
    int CH = (L + 7) / 8;
    int t0 = ch * CH, t1 = min(t0 + CH, L);
    if (t0 >= L) return;
    const size_t base = (size_t)b * L * DM_ + d;
    float w = 0.f;
    for (int j = -12; j <= 12; j++) {
        int tt = t0 + j; tt = tt < 0 ? 0 : (tt >= L ? L-1 : tt);
        w += R[base + (size_t)tt * DM_];
    }
    for (int t = t0; t < t1; t++) {
        size_t idx = base + (size_t)t * DM_;
        float cur = R[idx];
        float m = w * (1.0f/25.0f);
        float sv = cur - m;
        S[idx] = sv;
        bf h = __float2bfloat16(sv);
        SH[idx] = h; SL[idx] = __float2bfloat16(sv - __bfloat162float(h));
        if (tmode == 1) T[idx] = m;
        else if (tmode == 2) T[idx] += m;
        int ta = t + 13; ta = ta >= L ? L-1 : ta;
        int tr = t - 12; tr = tr < 0 ? 0 : tr;
        w += R[base + (size_t)ta * DM_] - R[base + (size_t)tr * DM_];
    }
}

__global__ void k_ln(const float* __restrict__ X, const float* __restrict__ g,
                     const float* __restrict__ be, float* __restrict__ Y) {
    int row = blockIdx.x, tid = threadIdx.x;
    __shared__ float buf[DM_];
    __shared__ float red[256];
    __shared__ float smu, sinv;
    const float* xr = X + (size_t)row * DM_;
    float s = 0.f;
    for (int i = tid; i < DM_; i += 256) { float v = xr[i]; buf[i] = v; s += v; }
    red[tid] = s; __syncthreads();
    for (int st = 128; st > 0; st >>= 1) { if (tid < st) red[tid] += red[tid+st]; __syncthreads(); }
    if (tid == 0) smu = red[0] * (1.0f/DM_);
    __syncthreads();
    float mu = smu, s2 = 0.f;
    for (int i = tid; i < DM_; i += 256) { float dv = buf[i] - mu; s2 += dv*dv; }
    red[tid] = s2; __syncthreads();
    for (int st = 128; st > 0; st >>= 1) { if (tid < st) red[tid] += red[tid+st]; __syncthreads(); }
    if (tid == 0) sinv = rsqrtf(red[0] * (1.0f/DM_) + 1e-5f);
    __syncthreads();
    float inv = sinv;
    for (int i = tid; i < DM_; i += 256)
        Y[(size_t)row*DM_ + i] = (buf[i] - mu) * inv * g[i] + be[i];
}

__global__ void k_submean2(float* __restrict__ Y, bf* __restrict__ H, bf* __restrict__ L,
                           int Llen) {
    int b = blockIdx.x >> 3, c = blockIdx.x & 7;
    int dl = threadIdx.x & 63, tp = threadIdx.x >> 6;
    int d = c*64 + dl;
    size_t base = (size_t)b*Llen*DM_ + d;
    float s = 0.f;
    for (int t = tp; t < Llen; t += 4) s += Y[base + (size_t)t*DM_];
    __shared__ float red[4][64];
    red[tp][dl] = s; __syncthreads();
    if (tp == 0) red[0][dl] = (red[0][dl]+red[1][dl]+red[2][dl]+red[3][dl]) / (float)Llen;
    __syncthreads();
    float m = red[0][dl];
    for (int t = tp; t < Llen; t += 4) {
        size_t idx = base + (size_t)t*DM_;
        float v = Y[idx] - m;
        Y[idx] = v;
        if (H) {
            bf h = __float2bfloat16(v);
            H[idx] = h; L[idx] = __float2bfloat16(v - __bfloat162float(h));
        }
    }
}

__global__ void k_final(const float* __restrict__ XLN, const float* __restrict__ TS,
                        const float* __restrict__ meanb, const float* __restrict__ Wt,
                        const float* __restrict__ Wp, const float* __restrict__ bp,
                        float* __restrict__ out) {
    int p = blockIdx.x, b = blockIdx.y, tid = threadIdx.x;
    int t = LBL_ + p;
    int r0 = (t - 1 + LD_) % LD_;
    int r2 = (t + 1) % LD_;
    float acc[NC_];
    #pragma unroll
    for (int c = 0; c < NC_; c++) acc[c] = 0.f;
    for (int d = tid; d < DM_; d += 256) {
        float xv  = XLN[((size_t)b*LD_ + t )*DM_ + d];
        float tv0 = TS [((size_t)b*LD_ + r0)*DM_ + d];
        float tv1 = TS [((size_t)b*LD_ + t )*DM_ + d];
        float tv2 = TS [((size_t)b*LD_ + r2)*DM_ + d];
        #pragma unroll
        for (int c = 0; c < NC_; c++) {
            acc[c] += xv  * Wp[(size_t)d*NC_ + c]
                    + tv0 * Wt[((size_t)0*DM_ + d)*NC_ + c]
                    + tv1 * Wt[((size_t)1*DM_ + d)*NC_ + c]
                    + tv2 * Wt[((size_t)2*DM_ + d)*NC_ + c];
        }
    }
    __shared__ float red[256];
    for (int c = 0; c < NC_; c++) {
        red[tid] = acc[c]; __syncthreads();
        for (int st = 128; st > 0; st >>= 1) { if (tid < st) red[tid] += red[tid+st]; __syncthreads(); }
        if (tid == 0)
            out[((size_t)b*PRED_ + p)*NC_ + c] = red[0] + meanb[b*NC_ + c] + bp[c];
        __syncthreads();
    }
}

// ================= host orchestration =================
static bf *ABH, *ABL, *QBH, *QBL, *KBH, *KBL, *HBH, *HBL, *WBH, *WBL;
static bf *DBH, *DBL, *DQH, *DQL, *DKH, *DKL;

extern "C" void kernel_launch(void* const* d_in, const int* in_sizes, int n_in,
                              void* d_out, int out_size) {
    const float* x_enc      = (const float*)d_in[0];
    const float* x_mark_enc = (const float*)d_in[1];
    const float* x_mark_dec = (const float*)d_in[3];
    const float* W_enc_emb  = (const float*)d_in[4];
    const float* W_mark_enc = (const float*)d_in[5];
    const float* W_dec_emb  = (const float*)d_in[6];
    const float* W_mark_dec = (const float*)d_in[7];
    const float* eW_attn    = (const float*)d_in[8];
    const float* eb_attn    = (const float*)d_in[9];
    const float* eW1        = (const float*)d_in[10];
    const float* eW2        = (const float*)d_in[11];
    const float* eg         = (const float*)d_in[12];
    const float* ebeta      = (const float*)d_in[13];
    const float* sW         = (const float*)d_in[14];
    const float* sb         = (const float*)d_in[15];
    const float* cW         = (const float*)d_in[16];
    const float* cb         = (const float*)d_in[17];
    const float* dW1        = (const float*)d_in[18];
    const float* dW2        = (const float*)d_in[19];
    const float* W_trend    = (const float*)d_in[20];
    const float* dg         = (const float*)d_in[21];
    const float* dbeta      = (const float*)d_in[22];
    const float* Wproj      = (const float*)d_in[23];
    const float* bproj      = (const float*)d_in[24];
    float* out = (float*)d_out;

    static cudaStream_t s2 = nullptr;
    static cudaEvent_t ev0 = nullptr, ev1 = nullptr;
    if (!s2) {
        cudaStreamCreateWithFlags(&s2, cudaStreamNonBlocking);
        cudaEventCreateWithFlags(&ev0, cudaEventDisableTiming);
        cudaEventCreateWithFlags(&ev1, cudaEventDisableTiming);
    }

    cudaFuncSetAttribute(k_mma, cudaFuncAttributeMaxDynamicSharedMemorySize, SMEM_SZ);

    float* ws = nullptr;   cudaGetSymbolAddress((void**)&ws, g_ws);
    float* dws = nullptr;  cudaGetSymbolAddress((void**)&dws, g_dws);
    int* dly = nullptr;    cudaGetSymbolAddress((void**)&dly, g_delay);
    int* dly2 = nullptr;   cudaGetSymbolAddress((void**)&dly2, g_delay2);
    cudaGetSymbolAddress((void**)&ABH, g_abh);
    cudaGetSymbolAddress((void**)&ABL, g_abl);
    cudaGetSymbolAddress((void**)&QBH, g_qbh);
    cudaGetSymbolAddress((void**)&QBL, g_qbl);
    cudaGetSymbolAddress((void**)&KBH, g_kbh);
    cudaGetSymbolAddress((void**)&KBL, g_kbl);
    cudaGetSymbolAddress((void**)&HBH, g_hbh);
    cudaGetSymbolAddress((void**)&HBL, g_hbl);
    cudaGetSymbolAddress((void**)&WBH, g_wbh);
    cudaGetSymbolAddress((void**)&WBL, g_wbl);
    cudaGetSymbolAddress((void**)&DBH, g_dbh);
    cudaGetSymbolAddress((void**)&DBL, g_dbl);
    cudaGetSymbolAddress((void**)&DQH, g_dqh);
    cudaGetSymbolAddress((void**)&DQL, g_dql);
    cudaGetSymbolAddress((void**)&DKH, g_dkh);
    cudaGetSymbolAddress((void**)&DKL, g_dkl);

    float* XE   = ws + O_XE;
    float* XA   = ws + O_XA;
    float* XD   = ws + O_XD;
    float* Qb   = ws + O_Q;
    float* Vb   = ws + O_V;
    float* Tb   = ws + O_T;
    float* Gb   = ws + O_G;
    float* CORR = ws + O_CORR;
    float* ENC  = ws + O_ENC;
    float* TS   = ws + O_TS;
    float* SEA  = ws + O_SEA;
    float* MEANB= ws + O_MEAN;
    float* WGT  = ws + O_WGT;
    float* dT    = dws + OD_T;
    float* dG    = dws + OD_G;
    float* dCORR = dws + OD_CORR;
    float* dWGT  = dws + OD_WGT;

    // weights first (both streams need them), then fork
    k_cvtT_all<<<10240, dim3(32,8)>>>(eW_attn, eW1, eW2, sW, cW, dW1, dW2, WBH, WBL);
    cudaEventRecord(ev0, 0);
    cudaStreamWaitEvent(s2, ev0, 0);

    // ======== stream B: decoder self-attn chain + cross-Q projection ========
    k_sea<<<(B_*LE_*NC_ + 255)/256, 256, 0, s2>>>(x_enc, SEA);
    k_meanc<<<B_, 256, 0, s2>>>(x_enc, MEANB);
    k_embed_dec2<<<dim3((LD_+31)/32, B_, 2), 256, 0, s2>>>(SEA, x_mark_enc, x_mark_dec,
                                                           W_dec_emb, W_mark_dec, XD, DBH, DBL);
    {
        int n = 2 * B_*(LP_-LD_)*DM_;
        k_padzero2<<<(n+255)/256, 256, 0, s2>>>(DQH, DQL, DKH, DKL, LD_);
    }
    k_mma<<<dim3(12,148,1), 256, SMEM_SZ, s2>>>(DBH, DBL, DM_, WBH+OW_SW, WBL+OW_SW, DM_,
        DM_, B_*LD_, 1536, 0, 0, 0,
        2, Qb, DM_, DQH, DQL, 0, DKH, DKL, LD_, LP_, 4, 4, nullptr, sb, 0);
    k_mma<<<dim3(5,5,B_), 256, SMEM_SZ, s2>>>(DQH, DQL, DM_, DKH, DKL, DM_,
        DM_, LD_, LD_, (long long)LP_*DM_, (long long)LP_*DM_, (long long)LD_*LD_,
        0, dG, LD_, nullptr, nullptr, 0, nullptr, nullptr, LD_, LD_, 0, 0, nullptr, nullptr, 0);
    k_zero<<<(B_*LD_ + 255)/256, 256, 0, s2>>>(dCORR, B_*LD_);
    k_corr2<<<dim3((LD_+15)/16, B_), 256, 0, s2>>>(dG, dCORR, LD_, LD_*LD_);
    k_topk<<<B_, 256, 0, s2>>>(dCORR, LD_, KT_D, dly2, dWGT);
    k_agg<<<dim3(LD_, B_), DM_, 0, s2>>>(Qb, DM_, dly2, dWGT, DBH, DBL,
                                         LD_, LD_, KT_D, (long long)LD_*DM_);
    k_mma<<<dim3(4,148,1), 256, SMEM_SZ, s2>>>(DBH, DBL, DM_,
        WBH+OW_SW+3*(size_t)DM_*DM_, WBL+OW_SW+3*(size_t)DM_*DM_, DM_,
        DM_, B_*LD_, DM_, 0, 0, 0,
        0, dT, DM_, nullptr, nullptr, 0, nullptr, nullptr, LD_, LD_, 0, 0, XD, sb+3*DM_, 0);
    k_add_decomp2<<<dim3(8, B_), DM_, 0, s2>>>(dT, XD, TS, DBH, DBL, LD_, 1);
    // cross-Q projection moved onto stream B (needs only DBH/DBL + weights)
    k_mma<<<dim3(4,148,1), 256, SMEM_SZ, s2>>>(DBH, DBL, DM_, WBH+OW_CW, WBL+OW_CW, DM_,
        DM_, B_*LD_, DM_, 0, 0, 0,
        1, nullptr, 0, DQH, DQL, DM_, nullptr, nullptr, LD_, LP_, 0, 0, nullptr, cb, 0);
    cudaEventRecord(ev1, s2);

    // ======== stream 0: encoder ========
    k_embed_enc2<<<dim3(LE_/32, B_, 2), 256>>>(x_enc, x_mark_enc, W_enc_emb, W_mark_enc, XE, ABH, ABL);

    float* x = XE;
    for (int l = 0; l < 2; l++) {
        const float* bb = eb_attn + (size_t)l*4*DM_;
        size_t wa = OW_EATT + (size_t)l*4*DM_*DM_;
        k_mma<<<dim3(12,128,1), 256, SMEM_SZ>>>(ABH, ABL, DM_, WBH+wa, WBL+wa, DM_,
            DM_, B_*LE_, 1536, 0, 0, 0,
            2, Vb, DM_, QBH, QBL, 0, KBH, KBL, LE_, LE_, 4, 4, nullptr, bb, 0);
        k_mma<<<dim3(4,4,B_), 256, SMEM_SZ>>>(QBH, QBL, DM_, KBH, KBL, DM_,
            DM_, LE_, LE_, (long long)LE_*DM_, (long long)LE_*DM_, (long long)LE_*LE_,
            0, Gb, LE_, nullptr, nullptr, 0, nullptr, nullptr, LE_, LE_, 0, 0, nullptr, nullptr, 0);
        k_zero<<<(B_*LE_ + 255)/256, 256>>>(CORR, B_*LE_);
        k_corr2<<<dim3(LE_/16, B_), 256>>>(Gb, CORR, LE_, LE_*LE_);
        k_topk<<<B_, 256>>>(CORR, LE_, KT_E, dly, WGT);
        k_agg<<<dim3(LE_, B_), DM_>>>(Vb, DM_, dly, WGT, ABH, ABL,
                                      LE_, LE_, KT_E, (long long)LE_*DM_);
        k_mma<<<dim3(4,128,1), 256, SMEM_SZ>>>(ABH, ABL, DM_,
            WBH+wa+3*(size_t)DM_*DM_, WBL+wa+3*(size_t)DM_*DM_, DM_,
            DM_, B_*LE_, DM_, 0, 0, 0,
            0, Tb, DM_, nullptr, nullptr, 0, nullptr, nullptr, LE_, LE_, 0, 0, x, bb+3*DM_, 0);
        float* nx = (x == XE) ? XA : XE;
        k_add_decomp2<<<dim3(8, B_), DM_>>>(Tb, nx, nullptr, ABH, ABL, LE_, 0);
        x = nx;
        k_mma<<<dim3(16,128,1), 256, SMEM_SZ>>>(ABH, ABL, DM_,
            WBH+OW_EW1+(size_t)l*DM_*DFF_, WBL+OW_EW1+(size_t)l*DM_*DFF_, DM_,
            DM_, B_*LE_, DFF_, 0, 0, 0,
            1, nullptr, 0, HBH, HBL, DFF_, nullptr, nullptr, LE_, LE_, 0, 0, nullptr, nullptr, 1);
        k_mma<<<dim3(4,128,1), 256, SMEM_SZ>>>(HBH, HBL, DFF_,
            WBH+OW_EW2+(size_t)l*DFF_*DM_, WBL+OW_EW2+(size_t)l*DFF_*DM_, DFF_,
            DFF_, B_*LE_, DM_, 0, 0, 0,
            0, Tb, DM_, nullptr, nullptr, 0, nullptr, nullptr, LE_, LE_, 0, 0, x, nullptr, 0);
        nx = (x == XE) ? XA : XE;
        k_add_decomp2<<<dim3(8, B_), DM_>>>(Tb, nx, nullptr, ABH, ABL, LE_, 0);
        x = nx;
    }
    k_ln<<<B_*LE_, 256>>>(x, eg, ebeta, ENC);
    k_submean2<<<B_*8, 256>>>(ENC, HBH, HBL, LE_);

    // cross-KV projection (needs only ENC split) — stays on stream 0 path
    {
        int n = B_*(LP_-LE_)*DM_;
        k_padzero<<<(n+255)/256, 256>>>(KBH, KBL, LE_);
    }
    k_mma<<<dim3(8,128,1), 256, SMEM_SZ>>>(HBH, HBL, DM_,
        WBH+OW_CW+(size_t)DM_*DM_, WBL+OW_CW+(size_t)DM_*DM_, DM_,
        DM_, B_*LE_, 1024, 0, 0, 0,
        3, Vb, DM_, nullptr, nullptr, 0, KBH, KBL, LE_, LP_, 0, 4, nullptr, cb+DM_, 0);

    // ---- join: Gram needs stream B's DQH (cross-Q) ----
    cudaStreamWaitEvent(0, ev1, 0);

    k_mma<<<dim3(5,5,B_), 256, SMEM_SZ>>>(DQH, DQL, DM_, KBH, KBL, DM_,
        DM_, LD_, LD_, (long long)LP_*DM_, (long long)LP_*DM_, (long long)LD_*LD_,
        0, Gb, LD_, nullptr, nullptr, 0, nullptr, nullptr, LD_, LD_, 0, 0, nullptr, nullptr, 0);
    k_zero<<<(B_*LD_ + 255)/256, 256>>>(CORR, B_*LD_);
    k_corr2<<<dim3((LD_+15)/16, B_), 256>>>(Gb, CORR, LD_, LD_*LD_);
    k_topk<<<B_, 256>>>(CORR, LD_, KT_D, dly, WGT);
    k_agg<<<dim3(LD_, B_), DM_>>>(Vb, DM_, dly, WGT, ABH, ABL,
                                  LD_, LE_, KT_D, (long long)LE_*DM_);
    k_mma<<<dim3(4,148,1), 256, SMEM_SZ>>>(ABH, ABL, DM_,
        WBH+OW_CW+3*(size_t)DM_*DM_, WBL+OW_CW+3*(size_t)DM_*DM_, DM_,
        DM_, B_*LD_, DM_, 0, 0, 0,
        0, Tb, DM_, nullptr, nullptr, 0, nullptr, nullptr, LD_, LD_, 0, 0, XD, cb+3*DM_, 0);
    k_add_decomp2<<<dim3(8, B_), DM_>>>(Tb, XE, TS, ABH, ABL, LD_, 2);

    // FFN
    k_mma<<<dim3(16,148,1), 256, SMEM_SZ>>>(ABH, ABL, DM_,
        WBH+OW_DW1, WBL+OW_DW1, DM_,
        DM_, B_*LD_, DFF_, 0, 0, 0,
        1, nullptr, 0, HBH, HBL, DFF_, nullptr, nullptr, LD_, LD_, 0, 0, nullptr, nullptr, 1);
    k_mma<<<dim3(4,148,1), 256, SMEM_SZ>>>(HBH, HBL, DFF_,
        WBH+OW_DW2, WBL+OW_DW2, DFF_,
        DFF_, B_*LD_, DM_, 0, 0, 0,
        0, Tb, DM_, nullptr, nullptr, 0, nullptr, nullptr, LD_, LD_, 0, 0, XE, nullptr, 0);
    k_add_decomp2<<<dim3(8, B_), DM_>>>(Tb, XA, TS, ABH, ABL, LD_, 2);

    // final layernorm + output assembly
    k_ln<<<B_*LD_, 256>>>(XA, dg, dbeta, Qb);
    k_submean2<<<B_*8, 256>>>(Qb, nullptr, nullptr, LD_);
    k_final<<<dim3(PRED_, B_), 256>>>(Qb, TS, MEANB, W_trend, Wproj, bproj, out);
}